// round 10
// baseline (speedup 1.0000x reference)
#include <cuda_runtime.h>
typedef unsigned int u32; typedef unsigned long long u64; typedef unsigned short u16;
#define NB 64
#define NN 512
#define NF 64

__device__ __align__(16) float g_Yrow[NB*NN*NF];     // Y=XW*cs row-major (diag adds)
__device__ __align__(16) uint4 g_Yfr [NB*64*8*32];   // [b][qj][n][lane] tf32 hi/lo frags of Y (P-gemm B)
__device__ __align__(16) uint4 g_XWfr[NB*8*8*8*32];  // [b][kt][qf][n][lane] tf32 frags of XW (S-gemm B)
__device__ __align__(16) uint4 g_XTfr[NB*8*4*8*32];  // [b][kt][qk][n][lane] bf16 frags of XW^T (H-gemm B)

__device__ __forceinline__ u32 smaddr(const void* p){
    u32 a; asm("{.reg .u64 t; cvta.to.shared.u64 t,%1; cvt.u32.u64 %0,t;}":"=r"(a):"l"(p)); return a;
}
__device__ __forceinline__ u32 t32(float x){ u32 r; asm("cvt.rna.tf32.f32 %0,%1;":"=r"(r):"f"(x)); return r; }
__device__ __forceinline__ void tsplit(float x, u32& h, u32& l){ h=t32(x); l=t32(x-__uint_as_float(h)); }
__device__ __forceinline__ u32 cvt2(float hi,float lo){ u32 r; asm("cvt.rn.bf16x2.f32 %0,%1,%2;":"=r"(r):"f"(hi),"f"(lo)); return r; }
__device__ __forceinline__ float bflo(u32 p){ return __uint_as_float(p<<16); }
__device__ __forceinline__ float bfhi(u32 p){ return __uint_as_float(p&0xFFFF0000u); }
__device__ __forceinline__ float tanhf_(float x){ float y; asm("tanh.approx.f32 %0,%1;":"=f"(y):"f"(x)); return y; }

#define MMAT(d,a,b0,b1) asm volatile( \
 "mma.sync.aligned.m16n8k8.row.col.f32.tf32.tf32.f32 {%0,%1,%2,%3},{%4,%5,%6,%7},{%8,%9},{%0,%1,%2,%3};" \
 : "+f"((d)[0]),"+f"((d)[1]),"+f"((d)[2]),"+f"((d)[3]) \
 : "r"((a)[0]),"r"((a)[1]),"r"((a)[2]),"r"((a)[3]),"r"(b0),"r"(b1))
#define MMAB(d,a,b0,b1) asm volatile( \
 "mma.sync.aligned.m16n8k16.row.col.f32.bf16.bf16.f32 {%0,%1,%2,%3},{%4,%5,%6,%7},{%8,%9},{%0,%1,%2,%3};" \
 : "+f"((d)[0]),"+f"((d)[1]),"+f"((d)[2]),"+f"((d)[3]) \
 : "r"((a)[0]),"r"((a)[1]),"r"((a)[2]),"r"((a)[3]),"r"(b0),"r"(b1))
#define CPA(dst,src) asm volatile("cp.async.cg.shared.global [%0],[%1],16;"::"r"(dst),"l"(src):"memory")
#define CPC() asm volatile("cp.async.commit_group;":::"memory")
#define CPW(n) asm volatile("cp.async.wait_group %0;"::"n"(n):"memory")

// ---------------------------------------------------------------------------
// XW = X@W per 64-row tile; col_sum(a) computed locally; emit Yrow fp32 +
// fragment-packed B operands for all three gemms.
__global__ __launch_bounds__(256) void k_prep(const float* __restrict__ X, const float* __restrict__ W,
                                              const float* __restrict__ am){
    __shared__ __align__(16) float Ws[64][64];
    __shared__ __align__(16) float Xs[64][68];
    __shared__ float csp[4][64];
    __shared__ float csm[64];
    const int t=threadIdx.x, b=blockIdx.x>>3, kt=blockIdx.x&7, R0=blockIdx.x*64;
    {   // col_sum of a
        int f=t&63, seg=t>>6;
        float s=0.f;
        for(int i=seg;i<64;i+=4) s+=am[i*64+f];
        csp[seg][f]=s;
    }
    for(int i=t;i<64*64;i+=256) Ws[i>>6][i&63]=W[i];
    for(int i=t;i<64*64;i+=256) Xs[i>>6][i&63]=X[(size_t)(R0+(i>>6))*NF+(i&63)];
    __syncthreads();
    if(t<64) csm[t]=csp[0][t]+csp[1][t]+csp[2][t]+csp[3][t];
    {
        const int tx=t&15, ty=t>>4;
        float acc[4][4]={};
        for(int c=0;c<64;c++){
            float xv[4],wv[4];
#pragma unroll
            for(int ii=0;ii<4;ii++) xv[ii]=Xs[ty*4+ii][c];
#pragma unroll
            for(int jj=0;jj<4;jj++) wv[jj]=Ws[c][tx*4+jj];
#pragma unroll
            for(int ii=0;ii<4;ii++)
#pragma unroll
                for(int jj=0;jj<4;jj++) acc[ii][jj]+=xv[ii]*wv[jj];
        }
        __syncthreads();
#pragma unroll
        for(int ii=0;ii<4;ii++)
#pragma unroll
            for(int jj=0;jj<4;jj++) Xs[ty*4+ii][tx*4+jj]=acc[ii][jj];
    }
    __syncthreads();
    const int lane=t&31, g=lane>>2, tc=lane&3;
    // Yrow fp32
#pragma unroll
    for(int u=0;u<4;u++){
        int idx=t+256*u; int r=idx>>4, f4=idx&15;
        float4 v=*(float4*)&Xs[r][f4*4];
        v.x*=csm[f4*4]; v.y*=csm[f4*4+1]; v.z*=csm[f4*4+2]; v.w*=csm[f4*4+3];
        *(float4*)&g_Yrow[(size_t)(R0+r)*NF+f4*4]=v;
    }
    // Y frags (tf32): element (j=q*8+tc(+4), f=n*8+g)
#pragma unroll
    for(int u=0;u<8;u++){
        int idx=t+256*u; int n=(idx>>5)&7, q=idx>>8;
        int f=n*8+g; float cf=csm[f];
        uint4 v;
        tsplit(Xs[q*8+tc][f]*cf,   v.x, v.y);
        tsplit(Xs[q*8+tc+4][f]*cf, v.z, v.w);
        g_Yfr[((size_t)(b*64+kt*8+q)*8+n)*32+lane]=v;
    }
    // XW frags (tf32): element (k=n*8+g, f=qf*8+tc(+4))
#pragma unroll
    for(int u=0;u<8;u++){
        int idx=t+256*u; int n=(idx>>5)&7, qf=idx>>8;
        int kr=n*8+g;
        uint4 v;
        tsplit(Xs[kr][qf*8+tc],   v.x, v.y);
        tsplit(Xs[kr][qf*8+tc+4], v.z, v.w);
        g_XWfr[(((size_t)(b*8+kt)*8+qf)*8+n)*32+lane]=v;
    }
    // XT frags (bf16 pairs): element (k=qk*16+2tc(+1,+8,+9), d=n*8+g)
#pragma unroll
    for(int u=0;u<4;u++){
        int idx=t+256*u; int n=(idx>>5)&7, qk=idx>>8;
        int d=n*8+g, k0=qk*16+2*tc;
        float x0=Xs[k0][d], x1=Xs[k0+1][d], x2=Xs[k0+8][d], x3=Xs[k0+9][d];
        uint4 v;
        v.x=cvt2(x1,x0); v.z=cvt2(x1-bfhi(v.x), x0-bflo(v.x));
        v.y=cvt2(x3,x2); v.w=cvt2(x3-bfhi(v.y), x2-bflo(v.y));
        g_XTfr[(((size_t)(b*8+kt)*4+qk)*8+n)*32+lane]=v;
    }
}

// ---------------------------------------------------------------------------
// smem: A0[0,18432) A1[18432,36864) | Ps[0,34816) overlays A after phase A
// rs@36864  bas@37376  -> SMEMB 39424.  B-fragments are direct LDG (no smem).
#define SMEMB 39424
__global__ __launch_bounds__(256,2) void k_main(const float* __restrict__ A, const float* __restrict__ ba,
                                                const float* __restrict__ bW, float* __restrict__ H,
                                                const int* __restrict__ N32){
    extern __shared__ __align__(16) char sm[];
    float* Ps =(float*)sm;
    float* rs =(float*)(sm+36864);
    float* bas=(float*)(sm+37376);
    const int t=threadIdx.x, w=t>>5, lane=t&31, g=lane>>2, tc=lane&3;
    const int b=blockIdx.y, i0=blockIdx.x*128;
    const u32 sbase=smaddr(sm);
    bas[t]=ba[t]; bas[256+t]=ba[256+t];
    const int nb = (__ldg(&N32[1])!=0) ? __ldg(&N32[b]) : __ldg(&N32[2*b]);
    const float* Ab = A + ((size_t)b*NN+i0)*NN;

    auto issueA=[&](int p,int it){
        const int j0=it*32;
#pragma unroll
        for(int u=0;u<4;u++){
            int idx=t+256*u; int r=idx>>3, c=idx&7;
            CPA(sbase + p*18432 + (u32)(r*36+c*4)*4, Ab + (size_t)r*NN + j0 + c*4);
        }
        CPC();
    };

    // ---- phase A: pacc = A @ Y over K=512 (16 iters of 32); Y frags via LDG ----
    float pacc[8][4]={}; float rloc=0.f;
    issueA(0,0);
    const uint4* yfr = g_Yfr + (size_t)b*64*256 + lane;
    for(int it=0; it<16; it++){
        const int p=it&1;
        if(it<15){ issueA(p^1,it+1); CPW(1); } else CPW(0);
        __syncthreads();
        const float* As=(const float*)(sm + p*18432);
        if(t<128){
            float s=0.f;
#pragma unroll
            for(int c=0;c<8;c++){ float4 v=*(const float4*)&As[t*36+c*4]; s+=v.x+v.y+v.z+v.w; }
            rloc+=s;
        }
#pragma unroll
        for(int q=0;q<4;q++){
            u32 ah[4],al[4];
            tsplit(As[(w*16+g  )*36+q*8+tc  ], ah[0],al[0]);
            tsplit(As[(w*16+g+8)*36+q*8+tc  ], ah[1],al[1]);
            tsplit(As[(w*16+g  )*36+q*8+tc+4], ah[2],al[2]);
            tsplit(As[(w*16+g+8)*36+q*8+tc+4], ah[3],al[3]);
            const uint4* yb = yfr + (size_t)(it*4+q)*256;
#pragma unroll
            for(int n=0;n<8;n++){
                uint4 v=__ldg(yb+n*32);
                MMAT(pacc[n],ah,v.x,v.z);
                MMAT(pacc[n],ah,v.y,v.w);
                MMAT(pacc[n],al,v.x,v.z);
            }
        }
        __syncthreads();
    }
    if(t<128) rs[t]=rloc + ((i0+t)<nb ? 1.f : 0.f);

    // ---- diag add + store P to smem fp32 (overlays A buffers) ----
    {
        const int il=i0+w*16+g, ih=il+8;
        const float* Yr=g_Yrow + (size_t)b*NN*NF;
#pragma unroll
        for(int n=0;n<8;n++){
            const int f=n*8+2*tc;
            if(il<nb){ pacc[n][0]+=Yr[(size_t)il*NF+f]; pacc[n][1]+=Yr[(size_t)il*NF+f+1]; }
            if(ih<nb){ pacc[n][2]+=Yr[(size_t)ih*NF+f]; pacc[n][3]+=Yr[(size_t)ih*NF+f+1]; }
            Ps[(w*16+g  )*68+f]  =pacc[n][0];
            Ps[(w*16+g  )*68+f+1]=pacc[n][1];
            Ps[(w*16+g+8)*68+f]  =pacc[n][2];
            Ps[(w*16+g+8)*68+f+1]=pacc[n][3];
        }
    }
    __syncthreads();

    // ---- phase B: sync-free; all B operands direct LDG.128 (L2-resident) ----
    float hacc[8][4]={};
    const float rv0=rs[w*16+g], rv1=rs[w*16+g+8];
    const uint4* wfr = g_XWfr + (size_t)b*8*2048 + lane;
    const uint4* tfr = g_XTfr + (size_t)b*8*1024 + lane;
    for(int kt=0;kt<8;kt++){
        float sacc[8][4]={};
#pragma unroll
        for(int qf=0;qf<8;qf++){
            u32 ph[4],pl[4];
            tsplit(Ps[(w*16+g  )*68+qf*8+tc  ], ph[0],pl[0]);
            tsplit(Ps[(w*16+g+8)*68+qf*8+tc  ], ph[1],pl[1]);
            tsplit(Ps[(w*16+g  )*68+qf*8+tc+4], ph[2],pl[2]);
            tsplit(Ps[(w*16+g+8)*68+qf*8+tc+4], ph[3],pl[3]);
            const uint4* wb = wfr + (size_t)(kt*8+qf)*256;
#pragma unroll
            for(int n=0;n<8;n++){
                uint4 v=__ldg(wb+n*32);
                MMAT(sacc[n],ph,v.x,v.z);
                MMAT(sacc[n],ph,v.y,v.w);
                MMAT(sacc[n],pl,v.x,v.z);
            }
        }
#pragma unroll
        for(int qk=0;qk<4;qk++){
            u32 Sh[4],Sl[4];
#pragma unroll
            for(int qq=0;qq<2;qq++){
                const int n=2*qk+qq;
                const int kc=kt*64+n*8+2*tc;
                const float b0v=bas[kc], b1v=bas[kc+1];
                float s0=tanhf_(sacc[n][0]+rv0*b0v);
                float s1=tanhf_(sacc[n][1]+rv0*b1v);
                float s2=tanhf_(sacc[n][2]+rv1*b0v);
                float s3=tanhf_(sacc[n][3]+rv1*b1v);
                Sh[2*qq]  =cvt2(s1,s0); Sl[2*qq]  =cvt2(s1-bfhi(Sh[2*qq]),  s0-bflo(Sh[2*qq]));
                Sh[2*qq+1]=cvt2(s3,s2); Sl[2*qq+1]=cvt2(s3-bfhi(Sh[2*qq+1]),s2-bflo(Sh[2*qq+1]));
            }
            const uint4* tb = tfr + (size_t)(kt*4+qk)*256;
#pragma unroll
            for(int n=0;n<8;n++){
                uint4 v=__ldg(tb+n*32);
                MMAB(hacc[n],Sh,v.x,v.y);
                MMAB(hacc[n],Sh,v.z,v.w);
                MMAB(hacc[n],Sl,v.x,v.y);
            }
        }
    }

    // ---- epilogue ----
    {
        const int il=i0+w*16+g, ih=il+8;
#pragma unroll
        for(int n=0;n<8;n++){
            const int d=n*8+2*tc;
            float2 v0, v1;
            v0.x=hacc[n][0]+bW[d]; v0.y=hacc[n][1]+bW[d+1];
            v1.x=hacc[n][2]+bW[d]; v1.y=hacc[n][3]+bW[d+1];
            *(float2*)&H[((size_t)b*NN+il)*NF+d]=v0;
            *(float2*)&H[((size_t)b*NN+ih)*NF+d]=v1;
        }
    }
}

// ---------------------------------------------------------------------------
extern "C" void kernel_launch(void* const* d_in, const int* in_sizes, int n_in,
                              void* d_out, int out_size){
    const float* X =(const float*)d_in[0];
    const float* A =(const float*)d_in[1];
    const int*   N =(const int*)d_in[2];
    const float* W =(const float*)d_in[3];
    const float* a =(const float*)d_in[4];
    const float* bW=(const float*)d_in[5];
    const float* ba=(const float*)d_in[6];
    float* H=(float*)d_out;
    cudaFuncSetAttribute(k_main, cudaFuncAttributeMaxDynamicSharedMemorySize, SMEMB);
    k_prep<<<NB*8,256>>>(X,W,a);
    k_main<<<dim3(4,NB),256,SMEMB>>>(A,ba,bW,H,N);
}

// round 11
// speedup vs baseline: 1.5204x; 1.5204x over previous
#include <cuda_runtime.h>
typedef unsigned int u32; typedef unsigned long long u64; typedef unsigned short u16;
#define NB 64
#define NN 512
#define NF 64

__device__ __align__(16) float g_Yrow[NB*NN*NF];     // Y=XW*cs row-major (diag adds)
__device__ __align__(16) uint4 g_Yfr [NB*32*8*32];   // [b][c16][n][lane] bf16 hi/lo k16-frags of Y
__device__ __align__(16) uint4 g_XWfr[NB*8*4*8*32];  // [b][kt][qf][n][lane] bf16 frags of XW (S-gemm B)
__device__ __align__(16) uint4 g_XTfr[NB*8*4*8*32];  // [b][kt][qk][n][lane] bf16 frags of XW^T (H-gemm B)

__device__ __forceinline__ u32 smaddr(const void* p){
    u32 a; asm("{.reg .u64 t; cvta.to.shared.u64 t,%1; cvt.u32.u64 %0,t;}":"=r"(a):"l"(p)); return a;
}
__device__ __forceinline__ u32 cvt2(float hi,float lo){ u32 r; asm("cvt.rn.bf16x2.f32 %0,%1,%2;":"=r"(r):"f"(hi),"f"(lo)); return r; }
__device__ __forceinline__ float bflo(u32 p){ return __uint_as_float(p<<16); }
__device__ __forceinline__ float bfhi(u32 p){ return __uint_as_float(p&0xFFFF0000u); }
__device__ __forceinline__ float tanhf_(float x){ float y; asm("tanh.approx.f32 %0,%1;":"=f"(y):"f"(x)); return y; }

#define MMAB(d,a,b0,b1) asm volatile( \
 "mma.sync.aligned.m16n8k16.row.col.f32.bf16.bf16.f32 {%0,%1,%2,%3},{%4,%5,%6,%7},{%8,%9},{%0,%1,%2,%3};" \
 : "+f"((d)[0]),"+f"((d)[1]),"+f"((d)[2]),"+f"((d)[3]) \
 : "r"((a)[0]),"r"((a)[1]),"r"((a)[2]),"r"((a)[3]),"r"(b0),"r"(b1))
#define CPA(dst,src) asm volatile("cp.async.cg.shared.global [%0],[%1],16;"::"r"(dst),"l"(src):"memory")
#define CPC() asm volatile("cp.async.commit_group;":::"memory")
#define CPW(n) asm volatile("cp.async.wait_group %0;"::"n"(n):"memory")

// ---------------------------------------------------------------------------
// XW = X@W per 64-row tile; col_sum(a) local; emit Yrow fp32 + 4-term bf16
// k16 fragment packs for all three gemms.
__global__ __launch_bounds__(256) void k_prep(const float* __restrict__ X, const float* __restrict__ W,
                                              const float* __restrict__ am){
    __shared__ __align__(16) float Ws[64][64];
    __shared__ __align__(16) float Xs[64][68];
    __shared__ float csp[4][64];
    __shared__ float csm[64];
    const int t=threadIdx.x, b=blockIdx.x>>3, kt=blockIdx.x&7, R0=blockIdx.x*64;
    {   // col_sum of a
        int f=t&63, seg=t>>6;
        float s=0.f;
        for(int i=seg;i<64;i+=4) s+=am[i*64+f];
        csp[seg][f]=s;
    }
    for(int i=t;i<64*64;i+=256) Ws[i>>6][i&63]=W[i];
    for(int i=t;i<64*64;i+=256) Xs[i>>6][i&63]=X[(size_t)(R0+(i>>6))*NF+(i&63)];
    __syncthreads();
    if(t<64) csm[t]=csp[0][t]+csp[1][t]+csp[2][t]+csp[3][t];
    {
        const int tx=t&15, ty=t>>4;
        float acc[4][4]={};
        for(int c4=0;c4<16;c4++){
            float4 xv[4]; float wv[4][4];
#pragma unroll
            for(int ii=0;ii<4;ii++) xv[ii]=*(float4*)&Xs[ty*4+ii][c4*4];
#pragma unroll
            for(int cc=0;cc<4;cc++) *(float4*)&wv[cc][0]=*(float4*)&Ws[c4*4+cc][tx*4];
#pragma unroll
            for(int ii=0;ii<4;ii++)
#pragma unroll
                for(int jj=0;jj<4;jj++)
                    acc[ii][jj]+=xv[ii].x*wv[0][jj]+xv[ii].y*wv[1][jj]+xv[ii].z*wv[2][jj]+xv[ii].w*wv[3][jj];
        }
        __syncthreads();
#pragma unroll
        for(int ii=0;ii<4;ii++)
#pragma unroll
            for(int jj=0;jj<4;jj++) Xs[ty*4+ii][tx*4+jj]=acc[ii][jj];
    }
    __syncthreads();
    const int lane=t&31, g=lane>>2, tc=lane&3;
    // Yrow fp32
#pragma unroll
    for(int u=0;u<4;u++){
        int idx=t+256*u; int r=idx>>4, f4=idx&15;
        float4 v=*(float4*)&Xs[r][f4*4];
        v.x*=csm[f4*4]; v.y*=csm[f4*4+1]; v.z*=csm[f4*4+2]; v.w*=csm[f4*4+3];
        *(float4*)&g_Yrow[(size_t)(R0+r)*NF+f4*4]=v;
    }
    // Y frags: chunk lc over j (k16), col f=n*8+g
#pragma unroll
    for(int u=0;u<4;u++){
        int idx=t+256*u; int n=(idx>>5)&7, lc=idx>>8;
        int j0=lc*16+2*tc, f=n*8+g; float cf=csm[f];
        float y0=Xs[j0][f]*cf, y1=Xs[j0+1][f]*cf, y2=Xs[j0+8][f]*cf, y3=Xs[j0+9][f]*cf;
        uint4 v;
        v.x=cvt2(y1,y0); v.z=cvt2(y1-bfhi(v.x), y0-bflo(v.x));
        v.y=cvt2(y3,y2); v.w=cvt2(y3-bfhi(v.y), y2-bflo(v.y));
        g_Yfr[((size_t)(b*32+kt*4+lc)*8+n)*32+lane]=v;
    }
    // XW frags (S-gemm B): col n*8+g = k row, chunk qf over f
#pragma unroll
    for(int u=0;u<4;u++){
        int idx=t+256*u; int n=(idx>>5)&7, qf=idx>>8;
        int k=n*8+g, f0=qf*16+2*tc;
        float x0=Xs[k][f0], x1=Xs[k][f0+1], x2=Xs[k][f0+8], x3=Xs[k][f0+9];
        uint4 v;
        v.x=cvt2(x1,x0); v.z=cvt2(x1-bfhi(v.x), x0-bflo(v.x));
        v.y=cvt2(x3,x2); v.w=cvt2(x3-bfhi(v.y), x2-bflo(v.y));
        g_XWfr[(((size_t)(b*8+kt)*4+qf)*8+n)*32+lane]=v;
    }
    // XT frags (H-gemm B): col n*8+g = d, chunk qk over k
#pragma unroll
    for(int u=0;u<4;u++){
        int idx=t+256*u; int n=(idx>>5)&7, qk=idx>>8;
        int d=n*8+g, k0=qk*16+2*tc;
        float x0=Xs[k0][d], x1=Xs[k0+1][d], x2=Xs[k0+8][d], x3=Xs[k0+9][d];
        uint4 v;
        v.x=cvt2(x1,x0); v.z=cvt2(x1-bfhi(v.x), x0-bflo(v.x));
        v.y=cvt2(x3,x2); v.w=cvt2(x3-bfhi(v.y), x2-bflo(v.y));
        g_XTfr[(((size_t)(b*8+kt)*4+qk)*8+n)*32+lane]=v;
    }
}

// ---------------------------------------------------------------------------
// smem (bytes): phase A: A0[0,18432) A1[18432,36864) Y0[36864,45056) Y1[45056,53248)
// phase B overlay: PH[0,18432) PL[18432,36864) XWf[36864,53248) XTf[53248,69632)
// rs@69632  bas@70144  -> SMEMB 72192
#define SMEMB 72192
__global__ __launch_bounds__(256,2) void k_main(const float* __restrict__ A, const float* __restrict__ ba,
                                                const float* __restrict__ bW, float* __restrict__ H,
                                                const int* __restrict__ N32){
    extern __shared__ __align__(16) char sm[];
    u32*  PH =(u32*)sm;                 // [128][36] bf16x2 hi pairs of P
    u32*  PL =(u32*)(sm+18432);
    float* rs =(float*)(sm+69632);
    float* bas=(float*)(sm+70144);
    const int t=threadIdx.x, w=t>>5, lane=t&31, g=lane>>2, tc=lane&3;
    const int b=blockIdx.y, i0=blockIdx.x*128;
    const u32 sbase=smaddr(sm);
    bas[t]=ba[t]; bas[256+t]=ba[256+t];
    const int nb = (__ldg(&N32[1])!=0) ? __ldg(&N32[b]) : __ldg(&N32[2*b]);
    const float* Ab = A + ((size_t)b*NN+i0)*NN;

    auto issueA=[&](int p,int it){
        const int j0=it*32;
#pragma unroll
        for(int u=0;u<4;u++){
            int idx=t+256*u; int r=idx>>3, c=idx&7;
            CPA(sbase + p*18432 + (u32)(r*36+c*4)*4, Ab + (size_t)r*NN + j0 + c*4);
        }
        const uint4* src=g_Yfr + (size_t)(b*32+it*2)*256;
#pragma unroll
        for(int u=0;u<2;u++){
            int idx=t+256*u;
            CPA(sbase + 36864 + p*8192 + (u32)idx*16, src+idx);
        }
        CPC();
    };

    // ---- phase A: pacc = A @ Y over K=512 (16 iters of 32, 2 k16-chunks each) ----
    float pacc[8][4]={}; float rloc=0.f;
    issueA(0,0);
    for(int it=0; it<16; it++){
        const int p=it&1;
        if(it<15){ issueA(p^1,it+1); CPW(1); } else CPW(0);
        __syncthreads();
        const float* As=(const float*)(sm + p*18432);
        if(t<128){
            float s=0.f;
#pragma unroll
            for(int c=0;c<8;c++){ float4 v=*(const float4*)&As[t*36+c*4]; s+=v.x+v.y+v.z+v.w; }
            rloc+=s;
        }
        const char* Yb = sm + 36864 + p*8192;
#pragma unroll
        for(int cc=0;cc<2;cc++){
            float2 f0=*(const float2*)&As[(w*16+g  )*36+cc*16+2*tc];
            float2 f1=*(const float2*)&As[(w*16+g+8)*36+cc*16+2*tc];
            float2 f2=*(const float2*)&As[(w*16+g  )*36+cc*16+8+2*tc];
            float2 f3=*(const float2*)&As[(w*16+g+8)*36+cc*16+8+2*tc];
            u32 AH[4],AL[4];
            AH[0]=cvt2(f0.y,f0.x); AL[0]=cvt2(f0.y-bfhi(AH[0]), f0.x-bflo(AH[0]));
            AH[1]=cvt2(f1.y,f1.x); AL[1]=cvt2(f1.y-bfhi(AH[1]), f1.x-bflo(AH[1]));
            AH[2]=cvt2(f2.y,f2.x); AL[2]=cvt2(f2.y-bfhi(AH[2]), f2.x-bflo(AH[2]));
            AH[3]=cvt2(f3.y,f3.x); AL[3]=cvt2(f3.y-bfhi(AH[3]), f3.x-bflo(AH[3]));
            const uint4* yb=(const uint4*)(Yb + cc*4096) + lane;
#pragma unroll
            for(int n=0;n<8;n++){
                uint4 v=yb[n*32];
                MMAB(pacc[n],AH,v.x,v.y);
                MMAB(pacc[n],AH,v.z,v.w);
                MMAB(pacc[n],AL,v.x,v.y);
                MMAB(pacc[n],AL,v.z,v.w);
            }
        }
        __syncthreads();
    }
    if(t<128) rs[t]=rloc + ((i0+t)<nb ? 1.f : 0.f);
    __syncthreads();  // all phase-A reads of A buffers done before PH/PL overwrite

    // ---- diag add + pre-split P into bf16x2 hi/lo smem ----
    {
        const int il=i0+w*16+g, ih=il+8;
        const float* Yr=g_Yrow + (size_t)b*NN*NF;
#pragma unroll
        for(int n=0;n<8;n++){
            const int f=n*8+2*tc;
            if(il<nb){ pacc[n][0]+=Yr[(size_t)il*NF+f]; pacc[n][1]+=Yr[(size_t)il*NF+f+1]; }
            if(ih<nb){ pacc[n][2]+=Yr[(size_t)ih*NF+f]; pacc[n][3]+=Yr[(size_t)ih*NF+f+1]; }
            u32 h0=cvt2(pacc[n][1],pacc[n][0]);
            u32 l0=cvt2(pacc[n][1]-bfhi(h0), pacc[n][0]-bflo(h0));
            u32 h1=cvt2(pacc[n][3],pacc[n][2]);
            u32 l1=cvt2(pacc[n][3]-bfhi(h1), pacc[n][2]-bflo(h1));
            PH[(w*16+g  )*36 + n*4+tc]=h0; PL[(w*16+g  )*36 + n*4+tc]=l0;
            PH[(w*16+g+8)*36 + n*4+tc]=h1; PL[(w*16+g+8)*36 + n*4+tc]=l1;
        }
    }
    __syncthreads();

    // ---- phase B: S = tanh(P@XW^T + r*ba); H += S@XW (4-term bf16, staged) ----
    float hacc[8][4]={};
    const float rv0=rs[w*16+g], rv1=rs[w*16+g+8];
    const uint4* XWfs=(const uint4*)(sm+36864);
    const uint4* XTfs=(const uint4*)(sm+53248);
    for(int kt=0;kt<8;kt++){
        __syncthreads();  // prior kt's reads done before restage
        {
            const uint4* sw=g_XWfr + (size_t)(b*8+kt)*1024;
            const uint4* st=g_XTfr + (size_t)(b*8+kt)*1024;
#pragma unroll
            for(int u=0;u<4;u++){ int idx=t+256*u; CPA(sbase+36864+(u32)idx*16, sw+idx); }
#pragma unroll
            for(int u=0;u<4;u++){ int idx=t+256*u; CPA(sbase+53248+(u32)idx*16, st+idx); }
            CPC(); CPW(0);
        }
        __syncthreads();
        float sacc[8][4]={};
#pragma unroll
        for(int qf=0;qf<4;qf++){
            u32 AH[4],AL[4];
            AH[0]=PH[(w*16+g  )*36 + qf*8+tc];   AL[0]=PL[(w*16+g  )*36 + qf*8+tc];
            AH[1]=PH[(w*16+g+8)*36 + qf*8+tc];   AL[1]=PL[(w*16+g+8)*36 + qf*8+tc];
            AH[2]=PH[(w*16+g  )*36 + qf*8+tc+4]; AL[2]=PL[(w*16+g  )*36 + qf*8+tc+4];
            AH[3]=PH[(w*16+g+8)*36 + qf*8+tc+4]; AL[3]=PL[(w*16+g+8)*36 + qf*8+tc+4];
            const uint4* wb=XWfs + qf*256 + lane;
#pragma unroll
            for(int n=0;n<8;n++){
                uint4 v=wb[n*32];
                MMAB(sacc[n],AH,v.x,v.y);
                MMAB(sacc[n],AH,v.z,v.w);
                MMAB(sacc[n],AL,v.x,v.y);
                MMAB(sacc[n],AL,v.z,v.w);
            }
        }
#pragma unroll
        for(int qk=0;qk<4;qk++){
            u32 Sh[4],Sl[4];
#pragma unroll
            for(int qq=0;qq<2;qq++){
                const int n=2*qk+qq;
                const int kc=kt*64+n*8+2*tc;
                const float b0v=bas[kc], b1v=bas[kc+1];
                float s0=tanhf_(sacc[n][0]+rv0*b0v);
                float s1=tanhf_(sacc[n][1]+rv0*b1v);
                float s2=tanhf_(sacc[n][2]+rv1*b0v);
                float s3=tanhf_(sacc[n][3]+rv1*b1v);
                Sh[2*qq]  =cvt2(s1,s0); Sl[2*qq]  =cvt2(s1-bfhi(Sh[2*qq]),  s0-bflo(Sh[2*qq]));
                Sh[2*qq+1]=cvt2(s3,s2); Sl[2*qq+1]=cvt2(s3-bfhi(Sh[2*qq+1]),s2-bflo(Sh[2*qq+1]));
            }
            const uint4* tb=XTfs + qk*256 + lane;
#pragma unroll
            for(int n=0;n<8;n++){
                uint4 v=tb[n*32];
                MMAB(hacc[n],Sh,v.x,v.y);
                MMAB(hacc[n],Sh,v.z,v.w);
                MMAB(hacc[n],Sl,v.x,v.y);
                MMAB(hacc[n],Sl,v.z,v.w);
            }
        }
    }

    // ---- epilogue ----
    {
        const int il=i0+w*16+g, ih=il+8;
#pragma unroll
        for(int n=0;n<8;n++){
            const int d=n*8+2*tc;
            float2 v0, v1;
            v0.x=hacc[n][0]+bW[d]; v0.y=hacc[n][1]+bW[d+1];
            v1.x=hacc[n][2]+bW[d]; v1.y=hacc[n][3]+bW[d+1];
            *(float2*)&H[((size_t)b*NN+il)*NF+d]=v0;
            *(float2*)&H[((size_t)b*NN+ih)*NF+d]=v1;
        }
    }
}

// ---------------------------------------------------------------------------
extern "C" void kernel_launch(void* const* d_in, const int* in_sizes, int n_in,
                              void* d_out, int out_size){
    const float* X =(const float*)d_in[0];
    const float* A =(const float*)d_in[1];
    const int*   N =(const int*)d_in[2];
    const float* W =(const float*)d_in[3];
    const float* a =(const float*)d_in[4];
    const float* bW=(const float*)d_in[5];
    const float* ba=(const float*)d_in[6];
    float* H=(float*)d_out;
    cudaFuncSetAttribute(k_main, cudaFuncAttributeMaxDynamicSharedMemorySize, SMEMB);
    k_prep<<<NB*8,256>>>(X,W,a);
    k_main<<<dim3(4,NB),256,SMEMB>>>(A,ba,bW,H,N);
}

// round 12
// speedup vs baseline: 1.6775x; 1.1033x over previous
#include <cuda_runtime.h>
typedef unsigned int u32; typedef unsigned long long u64; typedef unsigned short u16;
#define NB 64
#define NN 512
#define NF 64

__device__ __align__(16) float g_Yrow[NB*NN*NF];     // Y=XW*cs row-major (diag adds)
__device__ __align__(16) uint4 g_Yfr [NB*32*8*32];   // [b][c16][n][lane] f16 hi/lo k16-frags of Y
__device__ __align__(16) uint4 g_XWfr[NB*8*4*8*32];  // [b][kt][qf][n][lane] f16 frags of XW (S-gemm B)
__device__ __align__(16) uint4 g_XTfr[NB*8*4*8*32];  // [b][kt][qk][n][lane] f16 frags of XW^T (H-gemm B)

__device__ __forceinline__ u32 smaddr(const void* p){
    u32 a; asm("{.reg .u64 t; cvta.to.shared.u64 t,%1; cvt.u32.u64 %0,t;}":"=r"(a):"l"(p)); return a;
}
__device__ __forceinline__ u32 cvt2h(float hi,float lo){ u32 r; asm("cvt.rn.f16x2.f32 %0,%1,%2;":"=r"(r):"f"(hi),"f"(lo)); return r; }
__device__ __forceinline__ float flo16(u32 p){ float f; asm("{.reg .b16 l,h; mov.b32 {l,h},%1; cvt.f32.f16 %0,l;}":"=f"(f):"r"(p)); return f; }
__device__ __forceinline__ float fhi16(u32 p){ float f; asm("{.reg .b16 l,h; mov.b32 {l,h},%1; cvt.f32.f16 %0,h;}":"=f"(f):"r"(p)); return f; }
__device__ __forceinline__ float tanhf_(float x){ float y; asm("tanh.approx.f32 %0,%1;":"=f"(y):"f"(x)); return y; }

#define MMAH(d,a,b0,b1) asm volatile( \
 "mma.sync.aligned.m16n8k16.row.col.f32.f16.f16.f32 {%0,%1,%2,%3},{%4,%5,%6,%7},{%8,%9},{%0,%1,%2,%3};" \
 : "+f"((d)[0]),"+f"((d)[1]),"+f"((d)[2]),"+f"((d)[3]) \
 : "r"((a)[0]),"r"((a)[1]),"r"((a)[2]),"r"((a)[3]),"r"(b0),"r"(b1))
#define CPA(dst,src) asm volatile("cp.async.cg.shared.global [%0],[%1],16;"::"r"(dst),"l"(src):"memory")
#define CPC() asm volatile("cp.async.commit_group;":::"memory")
#define CPW(n) asm volatile("cp.async.wait_group %0;"::"n"(n):"memory")

// ---------------------------------------------------------------------------
// XW = X@W per 64-row tile; col_sum(a) local; emit Yrow fp32 + 3-term fp16
// k16 fragment packs for all three gemms.
__global__ __launch_bounds__(256) void k_prep(const float* __restrict__ X, const float* __restrict__ W,
                                              const float* __restrict__ am){
    __shared__ __align__(16) float Ws[64][64];
    __shared__ __align__(16) float Xs[64][68];
    __shared__ float csp[4][64];
    __shared__ float csm[64];
    const int t=threadIdx.x, b=blockIdx.x>>3, kt=blockIdx.x&7, R0=blockIdx.x*64;
    {   // col_sum of a
        int f=t&63, seg=t>>6;
        float s=0.f;
        for(int i=seg;i<64;i+=4) s+=am[i*64+f];
        csp[seg][f]=s;
    }
    for(int i=t;i<64*64;i+=256) Ws[i>>6][i&63]=W[i];
    for(int i=t;i<64*64;i+=256) Xs[i>>6][i&63]=X[(size_t)(R0+(i>>6))*NF+(i&63)];
    __syncthreads();
    if(t<64) csm[t]=csp[0][t]+csp[1][t]+csp[2][t]+csp[3][t];
    {
        const int tx=t&15, ty=t>>4;
        float acc[4][4]={};
        for(int c4=0;c4<16;c4++){
            float4 xv[4]; float wv[4][4];
#pragma unroll
            for(int ii=0;ii<4;ii++) xv[ii]=*(float4*)&Xs[ty*4+ii][c4*4];
#pragma unroll
            for(int cc=0;cc<4;cc++) *(float4*)&wv[cc][0]=*(float4*)&Ws[c4*4+cc][tx*4];
#pragma unroll
            for(int ii=0;ii<4;ii++)
#pragma unroll
                for(int jj=0;jj<4;jj++)
                    acc[ii][jj]+=xv[ii].x*wv[0][jj]+xv[ii].y*wv[1][jj]+xv[ii].z*wv[2][jj]+xv[ii].w*wv[3][jj];
        }
        __syncthreads();
#pragma unroll
        for(int ii=0;ii<4;ii++)
#pragma unroll
            for(int jj=0;jj<4;jj++) Xs[ty*4+ii][tx*4+jj]=acc[ii][jj];
    }
    __syncthreads();
    const int lane=t&31, g=lane>>2, tc=lane&3;
    // Yrow fp32
#pragma unroll
    for(int u=0;u<4;u++){
        int idx=t+256*u; int r=idx>>4, f4=idx&15;
        float4 v=*(float4*)&Xs[r][f4*4];
        v.x*=csm[f4*4]; v.y*=csm[f4*4+1]; v.z*=csm[f4*4+2]; v.w*=csm[f4*4+3];
        *(float4*)&g_Yrow[(size_t)(R0+r)*NF+f4*4]=v;
    }
    // Y frags: chunk lc over j (k16), col f=n*8+g
#pragma unroll
    for(int u=0;u<4;u++){
        int idx=t+256*u; int n=(idx>>5)&7, lc=idx>>8;
        int j0=lc*16+2*tc, f=n*8+g; float cf=csm[f];
        float y0=Xs[j0][f]*cf, y1=Xs[j0+1][f]*cf, y2=Xs[j0+8][f]*cf, y3=Xs[j0+9][f]*cf;
        uint4 v;
        v.x=cvt2h(y1,y0); v.z=cvt2h(y1-fhi16(v.x), y0-flo16(v.x));
        v.y=cvt2h(y3,y2); v.w=cvt2h(y3-fhi16(v.y), y2-flo16(v.y));
        g_Yfr[((size_t)(b*32+kt*4+lc)*8+n)*32+lane]=v;
    }
    // XW frags (S-gemm B): col n*8+g = k row, chunk qf over f
#pragma unroll
    for(int u=0;u<4;u++){
        int idx=t+256*u; int n=(idx>>5)&7, qf=idx>>8;
        int k=n*8+g, f0=qf*16+2*tc;
        float x0=Xs[k][f0], x1=Xs[k][f0+1], x2=Xs[k][f0+8], x3=Xs[k][f0+9];
        uint4 v;
        v.x=cvt2h(x1,x0); v.z=cvt2h(x1-fhi16(v.x), x0-flo16(v.x));
        v.y=cvt2h(x3,x2); v.w=cvt2h(x3-fhi16(v.y), x2-flo16(v.y));
        g_XWfr[(((size_t)(b*8+kt)*4+qf)*8+n)*32+lane]=v;
    }
    // XT frags (H-gemm B): col n*8+g = d, chunk qk over k
#pragma unroll
    for(int u=0;u<4;u++){
        int idx=t+256*u; int n=(idx>>5)&7, qk=idx>>8;
        int d=n*8+g, k0=qk*16+2*tc;
        float x0=Xs[k0][d], x1=Xs[k0+1][d], x2=Xs[k0+8][d], x3=Xs[k0+9][d];
        uint4 v;
        v.x=cvt2h(x1,x0); v.z=cvt2h(x1-fhi16(v.x), x0-flo16(v.x));
        v.y=cvt2h(x3,x2); v.w=cvt2h(x3-fhi16(v.y), x2-flo16(v.y));
        g_XTfr[(((size_t)(b*8+kt)*4+qk)*8+n)*32+lane]=v;
    }
}

// ---------------------------------------------------------------------------
// smem (bytes): phase A: A0[0,18432) A1[18432,36864) Y0[36864,45056) Y1[45056,53248)
// phase B overlay: PH[0,18432) PL[18432,36864) XWf[36864,53248) XTf[53248,69632)
// rs@69632  bas@70144  -> SMEMB 72192
#define SMEMB 72192
__global__ __launch_bounds__(256,2) void k_main(const float* __restrict__ A, const float* __restrict__ ba,
                                                const float* __restrict__ bW, float* __restrict__ H,
                                                const int* __restrict__ N32){
    extern __shared__ __align__(16) char sm[];
    u32*  PH =(u32*)sm;                 // [128][36] f16x2 hi pairs of P
    u32*  PL =(u32*)(sm+18432);
    float* rs =(float*)(sm+69632);
    float* bas=(float*)(sm+70144);
    const int t=threadIdx.x, w=t>>5, lane=t&31, g=lane>>2, tc=lane&3;
    const int b=blockIdx.y, i0=blockIdx.x*128;
    const u32 sbase=smaddr(sm);
    bas[t]=ba[t]; bas[256+t]=ba[256+t];
    const int nb = (__ldg(&N32[1])!=0) ? __ldg(&N32[b]) : __ldg(&N32[2*b]);
    const float* Ab = A + ((size_t)b*NN+i0)*NN;

    auto issueA=[&](int p,int it){
        const int j0=it*32;
#pragma unroll
        for(int u=0;u<4;u++){
            int idx=t+256*u; int r=idx>>3, c=idx&7;
            CPA(sbase + p*18432 + (u32)(r*36+c*4)*4, Ab + (size_t)r*NN + j0 + c*4);
        }
        const uint4* src=g_Yfr + (size_t)(b*32+it*2)*256;
#pragma unroll
        for(int u=0;u<2;u++){
            int idx=t+256*u;
            CPA(sbase + 36864 + p*8192 + (u32)idx*16, src+idx);
        }
        CPC();
    };

    // ---- phase A: pacc = A @ Y over K=512 (16 iters of 32, 2 k16-chunks each) ----
    float pacc[8][4]={}; float rloc=0.f;
    issueA(0,0);
    for(int it=0; it<16; it++){
        const int p=it&1;
        if(it<15){ issueA(p^1,it+1); CPW(1); } else CPW(0);
        __syncthreads();
        const float* As=(const float*)(sm + p*18432);
        if(t<128){
            float s=0.f;
#pragma unroll
            for(int c=0;c<8;c++){ float4 v=*(const float4*)&As[t*36+c*4]; s+=v.x+v.y+v.z+v.w; }
            rloc+=s;
        }
        const char* Yb = sm + 36864 + p*8192;
#pragma unroll
        for(int cc=0;cc<2;cc++){
            float2 f0=*(const float2*)&As[(w*16+g  )*36+cc*16+2*tc];
            float2 f1=*(const float2*)&As[(w*16+g+8)*36+cc*16+2*tc];
            float2 f2=*(const float2*)&As[(w*16+g  )*36+cc*16+8+2*tc];
            float2 f3=*(const float2*)&As[(w*16+g+8)*36+cc*16+8+2*tc];
            u32 AH[4],AL[4];
            AH[0]=cvt2h(f0.y,f0.x); AL[0]=cvt2h(f0.y-fhi16(AH[0]), f0.x-flo16(AH[0]));
            AH[1]=cvt2h(f1.y,f1.x); AL[1]=cvt2h(f1.y-fhi16(AH[1]), f1.x-flo16(AH[1]));
            AH[2]=cvt2h(f2.y,f2.x); AL[2]=cvt2h(f2.y-fhi16(AH[2]), f2.x-flo16(AH[2]));
            AH[3]=cvt2h(f3.y,f3.x); AL[3]=cvt2h(f3.y-fhi16(AH[3]), f3.x-flo16(AH[3]));
            const uint4* yb=(const uint4*)(Yb + cc*4096) + lane;
#pragma unroll
            for(int n=0;n<8;n++){
                uint4 v=yb[n*32];
                MMAH(pacc[n],AH,v.x,v.y);
                MMAH(pacc[n],AH,v.z,v.w);
                MMAH(pacc[n],AL,v.x,v.y);
            }
        }
        __syncthreads();
    }
    if(t<128) rs[t]=rloc + ((i0+t)<nb ? 1.f : 0.f);
    __syncthreads();  // all phase-A reads of A buffers done before PH/PL overwrite

    // ---- diag add + pre-split P into f16x2 hi/lo smem ----
    {
        const int il=i0+w*16+g, ih=il+8;
        const float* Yr=g_Yrow + (size_t)b*NN*NF;
#pragma unroll
        for(int n=0;n<8;n++){
            const int f=n*8+2*tc;
            if(il<nb){ pacc[n][0]+=Yr[(size_t)il*NF+f]; pacc[n][1]+=Yr[(size_t)il*NF+f+1]; }
            if(ih<nb){ pacc[n][2]+=Yr[(size_t)ih*NF+f]; pacc[n][3]+=Yr[(size_t)ih*NF+f+1]; }
            u32 h0=cvt2h(pacc[n][1],pacc[n][0]);
            u32 l0=cvt2h(pacc[n][1]-fhi16(h0), pacc[n][0]-flo16(h0));
            u32 h1=cvt2h(pacc[n][3],pacc[n][2]);
            u32 l1=cvt2h(pacc[n][3]-fhi16(h1), pacc[n][2]-flo16(h1));
            PH[(w*16+g  )*36 + n*4+tc]=h0; PL[(w*16+g  )*36 + n*4+tc]=l0;
            PH[(w*16+g+8)*36 + n*4+tc]=h1; PL[(w*16+g+8)*36 + n*4+tc]=l1;
        }
    }
    __syncthreads();

    // ---- phase B: S = tanh(P@XW^T + r*ba); H += S@XW (3-term fp16, staged) ----
    float hacc[8][4]={};
    const float rv0=rs[w*16+g], rv1=rs[w*16+g+8];
    const uint4* XWfs=(const uint4*)(sm+36864);
    const uint4* XTfs=(const uint4*)(sm+53248);
    for(int kt=0;kt<8;kt++){
        __syncthreads();  // prior kt's reads done before restage
        {
            const uint4* sw=g_XWfr + (size_t)(b*8+kt)*1024;
            const uint4* st=g_XTfr + (size_t)(b*8+kt)*1024;
#pragma unroll
            for(int u=0;u<4;u++){ int idx=t+256*u; CPA(sbase+36864+(u32)idx*16, sw+idx); }
#pragma unroll
            for(int u=0;u<4;u++){ int idx=t+256*u; CPA(sbase+53248+(u32)idx*16, st+idx); }
            CPC(); CPW(0);
        }
        __syncthreads();
        float sacc[8][4]={};
#pragma unroll
        for(int qf=0;qf<4;qf++){
            u32 AH[4],AL[4];
            AH[0]=PH[(w*16+g  )*36 + qf*8+tc];   AL[0]=PL[(w*16+g  )*36 + qf*8+tc];
            AH[1]=PH[(w*16+g+8)*36 + qf*8+tc];   AL[1]=PL[(w*16+g+8)*36 + qf*8+tc];
            AH[2]=PH[(w*16+g  )*36 + qf*8+tc+4]; AL[2]=PL[(w*16+g  )*36 + qf*8+tc+4];
            AH[3]=PH[(w*16+g+8)*36 + qf*8+tc+4]; AL[3]=PL[(w*16+g+8)*36 + qf*8+tc+4];
            const uint4* wb=XWfs + qf*256 + lane;
#pragma unroll
            for(int n=0;n<8;n++){
                uint4 v=wb[n*32];
                MMAH(sacc[n],AH,v.x,v.y);
                MMAH(sacc[n],AH,v.z,v.w);
                MMAH(sacc[n],AL,v.x,v.y);
            }
        }
#pragma unroll
        for(int qk=0;qk<4;qk++){
            u32 Sh[4],Sl[4];
#pragma unroll
            for(int qq=0;qq<2;qq++){
                const int n=2*qk+qq;
                const int kc=kt*64+n*8+2*tc;
                const float b0v=bas[kc], b1v=bas[kc+1];
                float s0=tanhf_(sacc[n][0]+rv0*b0v);
                float s1=tanhf_(sacc[n][1]+rv0*b1v);
                float s2=tanhf_(sacc[n][2]+rv1*b0v);
                float s3=tanhf_(sacc[n][3]+rv1*b1v);
                Sh[2*qq]  =cvt2h(s1,s0); Sl[2*qq]  =cvt2h(s1-fhi16(Sh[2*qq]),  s0-flo16(Sh[2*qq]));
                Sh[2*qq+1]=cvt2h(s3,s2); Sl[2*qq+1]=cvt2h(s3-fhi16(Sh[2*qq+1]),s2-flo16(Sh[2*qq+1]));
            }
            const uint4* tb=XTfs + qk*256 + lane;
#pragma unroll
            for(int n=0;n<8;n++){
                uint4 v=tb[n*32];
                MMAH(hacc[n],Sh,v.x,v.y);
                MMAH(hacc[n],Sh,v.z,v.w);
                MMAH(hacc[n],Sl,v.x,v.y);
            }
        }
    }

    // ---- epilogue ----
    {
        const int il=i0+w*16+g, ih=il+8;
#pragma unroll
        for(int n=0;n<8;n++){
            const int d=n*8+2*tc;
            float2 v0, v1;
            v0.x=hacc[n][0]+bW[d]; v0.y=hacc[n][1]+bW[d+1];
            v1.x=hacc[n][2]+bW[d]; v1.y=hacc[n][3]+bW[d+1];
            *(float2*)&H[((size_t)b*NN+il)*NF+d]=v0;
            *(float2*)&H[((size_t)b*NN+ih)*NF+d]=v1;
        }
    }
}

// ---------------------------------------------------------------------------
extern "C" void kernel_launch(void* const* d_in, const int* in_sizes, int n_in,
                              void* d_out, int out_size){
    const float* X =(const float*)d_in[0];
    const float* A =(const float*)d_in[1];
    const int*   N =(const int*)d_in[2];
    const float* W =(const float*)d_in[3];
    const float* a =(const float*)d_in[4];
    const float* bW=(const float*)d_in[5];
    const float* ba=(const float*)d_in[6];
    float* H=(float*)d_out;
    cudaFuncSetAttribute(k_main, cudaFuncAttributeMaxDynamicSharedMemorySize, SMEMB);
    k_prep<<<NB*8,256>>>(X,W,a);
    k_main<<<dim3(4,NB),256,SMEMB>>>(A,ba,bW,H,N);
}

// round 13
// speedup vs baseline: 1.7506x; 1.0436x over previous
#include <cuda_runtime.h>
typedef unsigned int u32; typedef unsigned long long u64; typedef unsigned short u16;
#define NB 64
#define NN 512
#define NF 64

__device__ __align__(16) float g_Yrow[NB*NN*NF];     // Y=XW*cs row-major (diag adds)
__device__ __align__(16) uint4 g_Yfr [NB*32*8*32];   // [b][c16][n][lane] f16 hi/lo k16-frags of Y
__device__ __align__(16) uint4 g_XWfr[NB*8*4*8*32];  // [b][kt][qf][n][lane] f16 frags of XW (S-gemm B)
__device__ __align__(16) uint4 g_XTfr[NB*8*4*8*32];  // [b][kt][qk][n][lane] f16 frags of XW^T (H-gemm B)

__device__ __forceinline__ u32 smaddr(const void* p){
    u32 a; asm("{.reg .u64 t; cvta.to.shared.u64 t,%1; cvt.u32.u64 %0,t;}":"=r"(a):"l"(p)); return a;
}
__device__ __forceinline__ u32 cvt2h(float hi,float lo){ u32 r; asm("cvt.rn.f16x2.f32 %0,%1,%2;":"=r"(r):"f"(hi),"f"(lo)); return r; }
__device__ __forceinline__ float flo16(u32 p){ float f; asm("{.reg .b16 l,h; mov.b32 {l,h},%1; cvt.f32.f16 %0,l;}":"=f"(f):"r"(p)); return f; }
__device__ __forceinline__ float fhi16(u32 p){ float f; asm("{.reg .b16 l,h; mov.b32 {l,h},%1; cvt.f32.f16 %0,h;}":"=f"(f):"r"(p)); return f; }
__device__ __forceinline__ float tanhf_(float x){ float y; asm("tanh.approx.f32 %0,%1;":"=f"(y):"f"(x)); return y; }

#define MMAH(d,a,b0,b1) asm volatile( \
 "mma.sync.aligned.m16n8k16.row.col.f32.f16.f16.f32 {%0,%1,%2,%3},{%4,%5,%6,%7},{%8,%9},{%0,%1,%2,%3};" \
 : "+f"((d)[0]),"+f"((d)[1]),"+f"((d)[2]),"+f"((d)[3]) \
 : "r"((a)[0]),"r"((a)[1]),"r"((a)[2]),"r"((a)[3]),"r"(b0),"r"(b1))
#define CPA(dst,src) asm volatile("cp.async.cg.shared.global [%0],[%1],16;"::"r"(dst),"l"(src):"memory")
#define CPC() asm volatile("cp.async.commit_group;":::"memory")
#define CPW(n) asm volatile("cp.async.wait_group %0;"::"n"(n):"memory")

// ---------------------------------------------------------------------------
// XW = X@W per 64-row tile; col_sum(a) local; emit Yrow fp32 + 3-term fp16
// k16 fragment packs for all three gemms.
__global__ __launch_bounds__(256) void k_prep(const float* __restrict__ X, const float* __restrict__ W,
                                              const float* __restrict__ am){
    __shared__ __align__(16) float Ws[64][64];
    __shared__ __align__(16) float Xs[64][68];
    __shared__ float csp[4][64];
    __shared__ float csm[64];
    const int t=threadIdx.x, b=blockIdx.x>>3, kt=blockIdx.x&7, R0=blockIdx.x*64;
    {   // col_sum of a
        int f=t&63, seg=t>>6;
        float s=0.f;
        for(int i=seg;i<64;i+=4) s+=am[i*64+f];
        csp[seg][f]=s;
    }
    for(int i=t;i<64*64;i+=256) Ws[i>>6][i&63]=W[i];
    for(int i=t;i<64*64;i+=256) Xs[i>>6][i&63]=X[(size_t)(R0+(i>>6))*NF+(i&63)];
    __syncthreads();
    if(t<64) csm[t]=csp[0][t]+csp[1][t]+csp[2][t]+csp[3][t];
    {
        const int tx=t&15, ty=t>>4;
        float acc[4][4]={};
        for(int c4=0;c4<16;c4++){
            float4 xv[4]; float wv[4][4];
#pragma unroll
            for(int ii=0;ii<4;ii++) xv[ii]=*(float4*)&Xs[ty*4+ii][c4*4];
#pragma unroll
            for(int cc=0;cc<4;cc++) *(float4*)&wv[cc][0]=*(float4*)&Ws[c4*4+cc][tx*4];
#pragma unroll
            for(int ii=0;ii<4;ii++)
#pragma unroll
                for(int jj=0;jj<4;jj++)
                    acc[ii][jj]+=xv[ii].x*wv[0][jj]+xv[ii].y*wv[1][jj]+xv[ii].z*wv[2][jj]+xv[ii].w*wv[3][jj];
        }
        __syncthreads();
#pragma unroll
        for(int ii=0;ii<4;ii++)
#pragma unroll
            for(int jj=0;jj<4;jj++) Xs[ty*4+ii][tx*4+jj]=acc[ii][jj];
    }
    __syncthreads();
    const int lane=t&31, g=lane>>2, tc=lane&3;
    // Yrow fp32
#pragma unroll
    for(int u=0;u<4;u++){
        int idx=t+256*u; int r=idx>>4, f4=idx&15;
        float4 v=*(float4*)&Xs[r][f4*4];
        v.x*=csm[f4*4]; v.y*=csm[f4*4+1]; v.z*=csm[f4*4+2]; v.w*=csm[f4*4+3];
        *(float4*)&g_Yrow[(size_t)(R0+r)*NF+f4*4]=v;
    }
    // Y frags: chunk lc over j (k16), col f=n*8+g
#pragma unroll
    for(int u=0;u<4;u++){
        int idx=t+256*u; int n=(idx>>5)&7, lc=idx>>8;
        int j0=lc*16+2*tc, f=n*8+g; float cf=csm[f];
        float y0=Xs[j0][f]*cf, y1=Xs[j0+1][f]*cf, y2=Xs[j0+8][f]*cf, y3=Xs[j0+9][f]*cf;
        uint4 v;
        v.x=cvt2h(y1,y0); v.z=cvt2h(y1-fhi16(v.x), y0-flo16(v.x));
        v.y=cvt2h(y3,y2); v.w=cvt2h(y3-fhi16(v.y), y2-flo16(v.y));
        g_Yfr[((size_t)(b*32+kt*4+lc)*8+n)*32+lane]=v;
    }
    // XW frags (S-gemm B): col n*8+g = k row, chunk qf over f
#pragma unroll
    for(int u=0;u<4;u++){
        int idx=t+256*u; int n=(idx>>5)&7, qf=idx>>8;
        int k=n*8+g, f0=qf*16+2*tc;
        float x0=Xs[k][f0], x1=Xs[k][f0+1], x2=Xs[k][f0+8], x3=Xs[k][f0+9];
        uint4 v;
        v.x=cvt2h(x1,x0); v.z=cvt2h(x1-fhi16(v.x), x0-flo16(v.x));
        v.y=cvt2h(x3,x2); v.w=cvt2h(x3-fhi16(v.y), x2-flo16(v.y));
        g_XWfr[(((size_t)(b*8+kt)*4+qf)*8+n)*32+lane]=v;
    }
    // XT frags (H-gemm B): col n*8+g = d, chunk qk over k
#pragma unroll
    for(int u=0;u<4;u++){
        int idx=t+256*u; int n=(idx>>5)&7, qk=idx>>8;
        int d=n*8+g, k0=qk*16+2*tc;
        float x0=Xs[k0][d], x1=Xs[k0+1][d], x2=Xs[k0+8][d], x3=Xs[k0+9][d];
        uint4 v;
        v.x=cvt2h(x1,x0); v.z=cvt2h(x1-fhi16(v.x), x0-flo16(v.x));
        v.y=cvt2h(x3,x2); v.w=cvt2h(x3-fhi16(v.y), x2-flo16(v.y));
        g_XTfr[(((size_t)(b*8+kt)*4+qk)*8+n)*32+lane]=v;
    }
}

// ---------------------------------------------------------------------------
// smem (bytes):
//  phase A: A0[0,18432) A1[18432,36864) Y0[36864,45056) Y1[45056,53248)
//  phase B overlay: buf0 XW@0 XT@16384 | buf1 XW@32768 XT@49152
//  PLs@65536 (18432) | rs@83968 (512) | bas@84480 (2048)  -> SMEMB 86528
#define SMEMB 86528
__global__ __launch_bounds__(256,2) void k_main(const float* __restrict__ A, const float* __restrict__ ba,
                                                const float* __restrict__ bW, float* __restrict__ H,
                                                const int* __restrict__ N32){
    extern __shared__ __align__(16) char sm[];
    u32*  PLs=(u32*)(sm+65536);          // [128][36] f16x2 lo-residual pairs of P
    float* rs =(float*)(sm+83968);
    float* bas=(float*)(sm+84480);
    const int t=threadIdx.x, w=t>>5, lane=t&31, g=lane>>2, tc=lane&3;
    const int b=blockIdx.y, i0=blockIdx.x*128;
    const u32 sbase=smaddr(sm);
    bas[t]=ba[t]; bas[256+t]=ba[256+t];
    const int nb = (__ldg(&N32[1])!=0) ? __ldg(&N32[b]) : __ldg(&N32[2*b]);
    const float* Ab = A + ((size_t)b*NN+i0)*NN;

    auto issueA=[&](int p,int it){
        const int j0=it*32;
#pragma unroll
        for(int u=0;u<4;u++){
            int idx=t+256*u; int r=idx>>3, c=idx&7;
            CPA(sbase + p*18432 + (u32)(r*36+c*4)*4, Ab + (size_t)r*NN + j0 + c*4);
        }
        const uint4* src=g_Yfr + (size_t)(b*32+it*2)*256;
#pragma unroll
        for(int u=0;u<2;u++){
            int idx=t+256*u;
            CPA(sbase + 36864 + p*8192 + (u32)idx*16, src+idx);
        }
        CPC();
    };

    // ---- phase A: pacc = A @ Y over K=512 (16 iters of 32, 2 k16-chunks each) ----
    float pacc[8][4]={}; float rloc=0.f;
    issueA(0,0);
    for(int it=0; it<16; it++){
        const int p=it&1;
        if(it<15){ issueA(p^1,it+1); CPW(1); } else CPW(0);
        __syncthreads();
        const float* As=(const float*)(sm + p*18432);
        if(t<128){
            float s=0.f;
#pragma unroll
            for(int c=0;c<8;c++){ float4 v=*(const float4*)&As[t*36+c*4]; s+=v.x+v.y+v.z+v.w; }
            rloc+=s;
        }
        const char* Yb = sm + 36864 + p*8192;
#pragma unroll
        for(int cc=0;cc<2;cc++){
            float2 f0=*(const float2*)&As[(w*16+g  )*36+cc*16+2*tc];
            float2 f1=*(const float2*)&As[(w*16+g+8)*36+cc*16+2*tc];
            float2 f2=*(const float2*)&As[(w*16+g  )*36+cc*16+8+2*tc];
            float2 f3=*(const float2*)&As[(w*16+g+8)*36+cc*16+8+2*tc];
            u32 AH[4],AL[4];
            AH[0]=cvt2h(f0.y,f0.x); AL[0]=cvt2h(f0.y-fhi16(AH[0]), f0.x-flo16(AH[0]));
            AH[1]=cvt2h(f1.y,f1.x); AL[1]=cvt2h(f1.y-fhi16(AH[1]), f1.x-flo16(AH[1]));
            AH[2]=cvt2h(f2.y,f2.x); AL[2]=cvt2h(f2.y-fhi16(AH[2]), f2.x-flo16(AH[2]));
            AH[3]=cvt2h(f3.y,f3.x); AL[3]=cvt2h(f3.y-fhi16(AH[3]), f3.x-flo16(AH[3]));
            const uint4* yb=(const uint4*)(Yb + cc*4096) + lane;
#pragma unroll
            for(int n=0;n<8;n++){
                uint4 v=yb[n*32];
                MMAH(pacc[n],AH,v.x,v.y);
                MMAH(pacc[n],AH,v.z,v.w);
                MMAH(pacc[n],AL,v.x,v.y);
            }
        }
        __syncthreads();
    }
    if(t<128) rs[t]=rloc + ((i0+t)<nb ? 1.f : 0.f);

    // ---- prefetch phase-B kt=0 into buf0 (A/Y buffers drained by last sync) ----
    {
        const uint4* sw=g_XWfr + (size_t)(b*8)*1024;
        const uint4* st=g_XTfr + (size_t)(b*8)*1024;
#pragma unroll
        for(int u=0;u<4;u++){ int idx=t+256*u; CPA(sbase+(u32)idx*16, sw+idx); }
#pragma unroll
        for(int u=0;u<4;u++){ int idx=t+256*u; CPA(sbase+16384+(u32)idx*16, st+idx); }
        CPC();
    }

    // ---- diag add; P hi-frags -> registers (accumulator==A-frag layout), lo -> smem ----
    u32 PHr[4][4];
    {
        const int il=i0+w*16+g, ih=il+8;
        const float* Yr=g_Yrow + (size_t)b*NN*NF;
#pragma unroll
        for(int n=0;n<8;n++){
            const int f=n*8+2*tc;
            if(il<nb){ pacc[n][0]+=Yr[(size_t)il*NF+f]; pacc[n][1]+=Yr[(size_t)il*NF+f+1]; }
            if(ih<nb){ pacc[n][2]+=Yr[(size_t)ih*NF+f]; pacc[n][3]+=Yr[(size_t)ih*NF+f+1]; }
            u32 h0=cvt2h(pacc[n][1],pacc[n][0]);
            u32 l0=cvt2h(pacc[n][1]-fhi16(h0), pacc[n][0]-flo16(h0));
            u32 h1=cvt2h(pacc[n][3],pacc[n][2]);
            u32 l1=cvt2h(pacc[n][3]-fhi16(h1), pacc[n][2]-flo16(h1));
            PHr[n>>1][(n&1)?2:0]=h0;
            PHr[n>>1][(n&1)?3:1]=h1;
            PLs[(w*16+g  )*36 + n*4+tc]=l0;
            PLs[(w*16+g+8)*36 + n*4+tc]=l1;
        }
    }
    __syncthreads();  // rs + PLs visible; all warps ready for phase B

    // ---- phase B: S = tanh(P@XW^T + r*ba); H += S@XW (3-term fp16, dbl-buffered) ----
    float hacc[8][4]={};
    const float rv0=rs[w*16+g], rv1=rs[w*16+g+8];
    for(int kt=0;kt<8;kt++){
        const int p=kt&1;
        if(kt>0) __syncthreads();  // all warps past compute(kt-1): buf p^1 free
        if(kt<7){
            const uint4* sw=g_XWfr + (size_t)(b*8+kt+1)*1024;
            const uint4* st=g_XTfr + (size_t)(b*8+kt+1)*1024;
            const u32 dst=sbase+(u32)(p^1)*32768;
#pragma unroll
            for(int u=0;u<4;u++){ int idx=t+256*u; CPA(dst+(u32)idx*16, sw+idx); }
#pragma unroll
            for(int u=0;u<4;u++){ int idx=t+256*u; CPA(dst+16384+(u32)idx*16, st+idx); }
            CPC();
            CPW(1);   // group(kt) complete; group(kt+1) in flight
        } else {
            CPW(0);
        }
        __syncthreads();
        const uint4* XWfs=(const uint4*)(sm + p*32768);
        const uint4* XTfs=(const uint4*)(sm + p*32768 + 16384);
        float sacc[8][4]={};
#pragma unroll
        for(int qf=0;qf<4;qf++){
            u32 AL[4];
            AL[0]=PLs[(w*16+g  )*36 + qf*8+tc];
            AL[1]=PLs[(w*16+g+8)*36 + qf*8+tc];
            AL[2]=PLs[(w*16+g  )*36 + qf*8+tc+4];
            AL[3]=PLs[(w*16+g+8)*36 + qf*8+tc+4];
            const uint4* wb=XWfs + qf*256 + lane;
#pragma unroll
            for(int n=0;n<8;n++){
                uint4 v=wb[n*32];
                MMAH(sacc[n],PHr[qf],v.x,v.y);
                MMAH(sacc[n],PHr[qf],v.z,v.w);
                MMAH(sacc[n],AL,v.x,v.y);
            }
        }
#pragma unroll
        for(int qk=0;qk<4;qk++){
            u32 Sh[4],Sl[4];
#pragma unroll
            for(int qq=0;qq<2;qq++){
                const int n=2*qk+qq;
                const int kc=kt*64+n*8+2*tc;
                const float b0v=bas[kc], b1v=bas[kc+1];
                float s0=tanhf_(sacc[n][0]+rv0*b0v);
                float s1=tanhf_(sacc[n][1]+rv0*b1v);
                float s2=tanhf_(sacc[n][2]+rv1*b0v);
                float s3=tanhf_(sacc[n][3]+rv1*b1v);
                Sh[2*qq]  =cvt2h(s1,s0); Sl[2*qq]  =cvt2h(s1-fhi16(Sh[2*qq]),  s0-flo16(Sh[2*qq]));
                Sh[2*qq+1]=cvt2h(s3,s2); Sl[2*qq+1]=cvt2h(s3-fhi16(Sh[2*qq+1]),s2-flo16(Sh[2*qq+1]));
            }
            const uint4* tb=XTfs + qk*256 + lane;
#pragma unroll
            for(int n=0;n<8;n++){
                uint4 v=tb[n*32];
                MMAH(hacc[n],Sh,v.x,v.y);
                MMAH(hacc[n],Sh,v.z,v.w);
                MMAH(hacc[n],Sl,v.x,v.y);
            }
        }
    }

    // ---- epilogue ----
    {
        const int il=i0+w*16+g, ih=il+8;
#pragma unroll
        for(int n=0;n<8;n++){
            const int d=n*8+2*tc;
            float2 v0, v1;
            v0.x=hacc[n][0]+bW[d]; v0.y=hacc[n][1]+bW[d+1];
            v1.x=hacc[n][2]+bW[d]; v1.y=hacc[n][3]+bW[d+1];
            *(float2*)&H[((size_t)b*NN+il)*NF+d]=v0;
            *(float2*)&H[((size_t)b*NN+ih)*NF+d]=v1;
        }
    }
}

// ---------------------------------------------------------------------------
extern "C" void kernel_launch(void* const* d_in, const int* in_sizes, int n_in,
                              void* d_out, int out_size){
    const float* X =(const float*)d_in[0];
    const float* A =(const float*)d_in[1];
    const int*   N =(const int*)d_in[2];
    const float* W =(const float*)d_in[3];
    const float* a =(const float*)d_in[4];
    const float* bW=(const float*)d_in[5];
    const float* ba=(const float*)d_in[6];
    float* H=(float*)d_out;
    cudaFuncSetAttribute(k_main, cudaFuncAttributeMaxDynamicSharedMemorySize, SMEMB);
    k_prep<<<NB*8,256>>>(X,W,a);
    k_main<<<dim3(4,NB),256,SMEMB>>>(A,ba,bW,H,N);
}

// round 14
// speedup vs baseline: 1.7728x; 1.0127x over previous
#include <cuda_runtime.h>
typedef unsigned int u32; typedef unsigned long long u64; typedef unsigned short u16;
#define NB 64
#define NN 512
#define NF 64

__device__ __align__(16) float g_Yrow[NB*NN*NF];     // Y=XW*cs row-major (diag adds)
__device__ __align__(16) uint4 g_Yfr [NB*32*8*32];   // [b][c16][n][lane] f16 hi/lo k16-frags of Y
__device__ __align__(16) uint4 g_XWfr[NB*8*4*8*32];  // [b][kt][qf][n][lane] f16 frags of XW (S-gemm B)
__device__ __align__(16) uint4 g_XTfr[NB*8*4*8*32];  // [b][kt][qk][n][lane] f16 frags of XW^T (H-gemm B)

__device__ __forceinline__ u32 smaddr(const void* p){
    u32 a; asm("{.reg .u64 t; cvta.to.shared.u64 t,%1; cvt.u32.u64 %0,t;}":"=r"(a):"l"(p)); return a;
}
__device__ __forceinline__ u32 cvt2h(float hi,float lo){ u32 r; asm("cvt.rn.f16x2.f32 %0,%1,%2;":"=r"(r):"f"(hi),"f"(lo)); return r; }
__device__ __forceinline__ float flo16(u32 p){ float f; asm("{.reg .b16 l,h; mov.b32 {l,h},%1; cvt.f32.f16 %0,l;}":"=f"(f):"r"(p)); return f; }
__device__ __forceinline__ float fhi16(u32 p){ float f; asm("{.reg .b16 l,h; mov.b32 {l,h},%1; cvt.f32.f16 %0,h;}":"=f"(f):"r"(p)); return f; }
__device__ __forceinline__ float tanhf_(float x){ float y; asm("tanh.approx.f32 %0,%1;":"=f"(y):"f"(x)); return y; }

#define MMAH(d,a,b0,b1) asm volatile( \
 "mma.sync.aligned.m16n8k16.row.col.f32.f16.f16.f32 {%0,%1,%2,%3},{%4,%5,%6,%7},{%8,%9},{%0,%1,%2,%3};" \
 : "+f"((d)[0]),"+f"((d)[1]),"+f"((d)[2]),"+f"((d)[3]) \
 : "r"((a)[0]),"r"((a)[1]),"r"((a)[2]),"r"((a)[3]),"r"(b0),"r"(b1))
#define CPA(dst,src) asm volatile("cp.async.cg.shared.global [%0],[%1],16;"::"r"(dst),"l"(src):"memory")
#define CPC() asm volatile("cp.async.commit_group;":::"memory")
#define CPW(n) asm volatile("cp.async.wait_group %0;"::"n"(n):"memory")

// ---------------------------------------------------------------------------
// XW = X@W per 64-row tile (f16 3-term MMA); col_sum(a) local; emit Yrow fp32
// + 3-term fp16 k16 fragment packs for all three k_main gemms.
__global__ __launch_bounds__(256) void k_prep(const float* __restrict__ X, const float* __restrict__ W,
                                              const float* __restrict__ am){
    __shared__ __align__(16) float Ws[64][64];
    __shared__ __align__(16) float Xs[64][68];
    __shared__ __align__(16) uint4 Wfr[4][8][32];
    __shared__ float csp[4][64];
    __shared__ float csm[64];
    const int t=threadIdx.x, b=blockIdx.x>>3, kt=blockIdx.x&7, R0=blockIdx.x*64;
    const int w=t>>5, lane=t&31, g=lane>>2, tc=lane&3;
    {   // col_sum of a
        int f=t&63, seg=t>>6;
        float s=0.f;
        for(int i=seg;i<64;i+=4) s+=am[i*64+f];
        csp[seg][f]=s;
    }
    for(int i=t;i<64*64;i+=256) Ws[i>>6][i&63]=W[i];
    for(int i=t;i<64*64;i+=256) Xs[i>>6][i&63]=X[(size_t)(R0+(i>>6))*NF+(i&63)];
    __syncthreads();
    if(t<64) csm[t]=csp[0][t]+csp[1][t]+csp[2][t]+csp[3][t];
    // W B-fragments (f16 hi/lo, k16 chunks over input dim c)
    for(int u=t;u<1024;u+=256){
        int l2=u&31, n=(u>>5)&7, qc=u>>8;
        int gg=l2>>2, tcc=l2&3;
        int d=n*8+gg, c0=qc*16+2*tcc;
        float w0=Ws[c0][d], w1=Ws[c0+1][d], w2=Ws[c0+8][d], w3=Ws[c0+9][d];
        uint4 v;
        v.x=cvt2h(w1,w0); v.z=cvt2h(w1-fhi16(v.x), w0-flo16(v.x));
        v.y=cvt2h(w3,w2); v.w=cvt2h(w3-fhi16(v.y), w2-flo16(v.y));
        Wfr[qc][n][l2]=v;
    }
    __syncthreads();
    // XW = X@W via MMA: warp -> (m-frag w>>1, n-half w&1)
    const int mf=w>>1, nh=w&1;
    float acc[4][4]={};
#pragma unroll
    for(int qc=0;qc<4;qc++){
        float2 f0=*(float2*)&Xs[mf*16+g  ][qc*16+2*tc];
        float2 f1=*(float2*)&Xs[mf*16+g+8][qc*16+2*tc];
        float2 f2=*(float2*)&Xs[mf*16+g  ][qc*16+8+2*tc];
        float2 f3=*(float2*)&Xs[mf*16+g+8][qc*16+8+2*tc];
        u32 AH[4],AL[4];
        AH[0]=cvt2h(f0.y,f0.x); AL[0]=cvt2h(f0.y-fhi16(AH[0]), f0.x-flo16(AH[0]));
        AH[1]=cvt2h(f1.y,f1.x); AL[1]=cvt2h(f1.y-fhi16(AH[1]), f1.x-flo16(AH[1]));
        AH[2]=cvt2h(f2.y,f2.x); AL[2]=cvt2h(f2.y-fhi16(AH[2]), f2.x-flo16(AH[2]));
        AH[3]=cvt2h(f3.y,f3.x); AL[3]=cvt2h(f3.y-fhi16(AH[3]), f3.x-flo16(AH[3]));
#pragma unroll
        for(int nn=0;nn<4;nn++){
            uint4 v=Wfr[qc][nh*4+nn][lane];
            MMAH(acc[nn],AH,v.x,v.y);
            MMAH(acc[nn],AH,v.z,v.w);
            MMAH(acc[nn],AL,v.x,v.y);
        }
    }
    __syncthreads();   // all A-fragment reads of Xs done before overwrite
#pragma unroll
    for(int nn=0;nn<4;nn++){
        int d=(nh*4+nn)*8+2*tc;
        Xs[mf*16+g  ][d]=acc[nn][0]; Xs[mf*16+g  ][d+1]=acc[nn][1];
        Xs[mf*16+g+8][d]=acc[nn][2]; Xs[mf*16+g+8][d+1]=acc[nn][3];
    }
    __syncthreads();
    // Yrow fp32
#pragma unroll
    for(int u=0;u<4;u++){
        int idx=t+256*u; int r=idx>>4, f4=idx&15;
        float4 v=*(float4*)&Xs[r][f4*4];
        v.x*=csm[f4*4]; v.y*=csm[f4*4+1]; v.z*=csm[f4*4+2]; v.w*=csm[f4*4+3];
        *(float4*)&g_Yrow[(size_t)(R0+r)*NF+f4*4]=v;
    }
    // Y frags: chunk lc over j (k16), col f=n*8+g
#pragma unroll
    for(int u=0;u<4;u++){
        int idx=t+256*u; int n=(idx>>5)&7, lc=idx>>8;
        int j0=lc*16+2*tc, f=n*8+g; float cf=csm[f];
        float y0=Xs[j0][f]*cf, y1=Xs[j0+1][f]*cf, y2=Xs[j0+8][f]*cf, y3=Xs[j0+9][f]*cf;
        uint4 v;
        v.x=cvt2h(y1,y0); v.z=cvt2h(y1-fhi16(v.x), y0-flo16(v.x));
        v.y=cvt2h(y3,y2); v.w=cvt2h(y3-fhi16(v.y), y2-flo16(v.y));
        g_Yfr[((size_t)(b*32+kt*4+lc)*8+n)*32+lane]=v;
    }
    // XW frags (S-gemm B): col n*8+g = k row, chunk qf over f
#pragma unroll
    for(int u=0;u<4;u++){
        int idx=t+256*u; int n=(idx>>5)&7, qf=idx>>8;
        int k=n*8+g, f0=qf*16+2*tc;
        float x0=Xs[k][f0], x1=Xs[k][f0+1], x2=Xs[k][f0+8], x3=Xs[k][f0+9];
        uint4 v;
        v.x=cvt2h(x1,x0); v.z=cvt2h(x1-fhi16(v.x), x0-flo16(v.x));
        v.y=cvt2h(x3,x2); v.w=cvt2h(x3-fhi16(v.y), x2-flo16(v.y));
        g_XWfr[(((size_t)(b*8+kt)*4+qf)*8+n)*32+lane]=v;
    }
    // XT frags (H-gemm B): col n*8+g = d, chunk qk over k
#pragma unroll
    for(int u=0;u<4;u++){
        int idx=t+256*u; int n=(idx>>5)&7, qk=idx>>8;
        int d=n*8+g, k0=qk*16+2*tc;
        float x0=Xs[k0][d], x1=Xs[k0+1][d], x2=Xs[k0+8][d], x3=Xs[k0+9][d];
        uint4 v;
        v.x=cvt2h(x1,x0); v.z=cvt2h(x1-fhi16(v.x), x0-flo16(v.x));
        v.y=cvt2h(x3,x2); v.w=cvt2h(x3-fhi16(v.y), x2-flo16(v.y));
        g_XTfr[(((size_t)(b*8+kt)*4+qk)*8+n)*32+lane]=v;
    }
}

// ---------------------------------------------------------------------------
// smem (bytes):
//  phase A: A0[0,18432) A1[18432,36864) Y0[36864,45056) Y1[45056,53248)
//  phase B overlay: buf0 XW@0 XT@16384 | buf1 XW@32768 XT@49152
//  PLs@65536 (18432) | rs@83968 (512) | bas@84480 (2048)  -> SMEMB 86528
#define SMEMB 86528
__global__ __launch_bounds__(256,2) void k_main(const float* __restrict__ A, const float* __restrict__ ba,
                                                const float* __restrict__ bW, float* __restrict__ H,
                                                const int* __restrict__ N32){
    extern __shared__ __align__(16) char sm[];
    u32*  PLs=(u32*)(sm+65536);          // [128][36] f16x2 lo-residual pairs of P
    float* rs =(float*)(sm+83968);
    float* bas=(float*)(sm+84480);
    const int t=threadIdx.x, w=t>>5, lane=t&31, g=lane>>2, tc=lane&3;
    const int b=blockIdx.y, i0=blockIdx.x*128;
    const u32 sbase=smaddr(sm);
    bas[t]=ba[t]; bas[256+t]=ba[256+t];
    const int nb = (__ldg(&N32[1])!=0) ? __ldg(&N32[b]) : __ldg(&N32[2*b]);
    const float* Ab = A + ((size_t)b*NN+i0)*NN;

    auto issueA=[&](int p,int it){
        const int j0=it*32;
#pragma unroll
        for(int u=0;u<4;u++){
            int idx=t+256*u; int r=idx>>3, c=idx&7;
            CPA(sbase + p*18432 + (u32)(r*36+c*4)*4, Ab + (size_t)r*NN + j0 + c*4);
        }
        const uint4* src=g_Yfr + (size_t)(b*32+it*2)*256;
#pragma unroll
        for(int u=0;u<2;u++){
            int idx=t+256*u;
            CPA(sbase + 36864 + p*8192 + (u32)idx*16, src+idx);
        }
        CPC();
    };

    // ---- phase A: pacc = A @ Y over K=512 (16 iters; single sync per iter) ----
    float pacc[8][4]={}; float rloc=0.f;
    issueA(0,0);
    for(int it=0; it<16; it++){
        const int p=it&1;
        CPW(0);
        __syncthreads();           // publishes buf p; proves buf p^1 drained
        if(it<15) issueA(p^1,it+1);
        const float* As=(const float*)(sm + p*18432);
        if(t<128){
            float s=0.f;
#pragma unroll
            for(int c=0;c<8;c++){ float4 v=*(const float4*)&As[t*36+c*4]; s+=v.x+v.y+v.z+v.w; }
            rloc+=s;
        }
        const char* Yb = sm + 36864 + p*8192;
#pragma unroll
        for(int cc=0;cc<2;cc++){
            float2 f0=*(const float2*)&As[(w*16+g  )*36+cc*16+2*tc];
            float2 f1=*(const float2*)&As[(w*16+g+8)*36+cc*16+2*tc];
            float2 f2=*(const float2*)&As[(w*16+g  )*36+cc*16+8+2*tc];
            float2 f3=*(const float2*)&As[(w*16+g+8)*36+cc*16+8+2*tc];
            u32 AH[4],AL[4];
            AH[0]=cvt2h(f0.y,f0.x); AL[0]=cvt2h(f0.y-fhi16(AH[0]), f0.x-flo16(AH[0]));
            AH[1]=cvt2h(f1.y,f1.x); AL[1]=cvt2h(f1.y-fhi16(AH[1]), f1.x-flo16(AH[1]));
            AH[2]=cvt2h(f2.y,f2.x); AL[2]=cvt2h(f2.y-fhi16(AH[2]), f2.x-flo16(AH[2]));
            AH[3]=cvt2h(f3.y,f3.x); AL[3]=cvt2h(f3.y-fhi16(AH[3]), f3.x-flo16(AH[3]));
            const uint4* yb=(const uint4*)(Yb + cc*4096) + lane;
#pragma unroll
            for(int n=0;n<8;n++){
                uint4 v=yb[n*32];
                MMAH(pacc[n],AH,v.x,v.y);
                MMAH(pacc[n],AH,v.z,v.w);
                MMAH(pacc[n],AL,v.x,v.y);
            }
        }
    }
    if(t<128) rs[t]=rloc + ((i0+t)<nb ? 1.f : 0.f);
    __syncthreads();   // phase-A buffers fully drained before phase-B prefetch

    // ---- prefetch phase-B kt=0 into buf0 ----
    {
        const uint4* sw=g_XWfr + (size_t)(b*8)*1024;
        const uint4* st=g_XTfr + (size_t)(b*8)*1024;
#pragma unroll
        for(int u=0;u<4;u++){ int idx=t+256*u; CPA(sbase+(u32)idx*16, sw+idx); }
#pragma unroll
        for(int u=0;u<4;u++){ int idx=t+256*u; CPA(sbase+16384+(u32)idx*16, st+idx); }
        CPC();
    }

    // ---- diag add; P hi-frags -> registers (accumulator==A-frag layout), lo -> smem ----
    u32 PHr[4][4];
    {
        const int il=i0+w*16+g, ih=il+8;
        const float* Yr=g_Yrow + (size_t)b*NN*NF;
#pragma unroll
        for(int n=0;n<8;n++){
            const int f=n*8+2*tc;
            if(il<nb){ pacc[n][0]+=Yr[(size_t)il*NF+f]; pacc[n][1]+=Yr[(size_t)il*NF+f+1]; }
            if(ih<nb){ pacc[n][2]+=Yr[(size_t)ih*NF+f]; pacc[n][3]+=Yr[(size_t)ih*NF+f+1]; }
            u32 h0=cvt2h(pacc[n][1],pacc[n][0]);
            u32 l0=cvt2h(pacc[n][1]-fhi16(h0), pacc[n][0]-flo16(h0));
            u32 h1=cvt2h(pacc[n][3],pacc[n][2]);
            u32 l1=cvt2h(pacc[n][3]-fhi16(h1), pacc[n][2]-flo16(h1));
            PHr[n>>1][(n&1)?2:0]=h0;
            PHr[n>>1][(n&1)?3:1]=h1;
            PLs[(w*16+g  )*36 + n*4+tc]=l0;
            PLs[(w*16+g+8)*36 + n*4+tc]=l1;
        }
    }

    // ---- phase B: S = tanh(P@XW^T + r*ba); H += S@XW (3-term fp16, dbl-buffered,
    //      single sync per kt; kt=0's sync also publishes PLs/rs) ----
    float hacc[8][4]={};
    float rv0=0.f, rv1=0.f;
    for(int kt=0;kt<8;kt++){
        const int p=kt&1;
        CPW(0);
        __syncthreads();           // publishes buf p (+ PLs/rs at kt=0); buf p^1 drained
        if(kt==0){ rv0=rs[w*16+g]; rv1=rs[w*16+g+8]; }
        if(kt<7){
            const uint4* sw=g_XWfr + (size_t)(b*8+kt+1)*1024;
            const uint4* st=g_XTfr + (size_t)(b*8+kt+1)*1024;
            const u32 dst=sbase+(u32)(p^1)*32768;
#pragma unroll
            for(int u=0;u<4;u++){ int idx=t+256*u; CPA(dst+(u32)idx*16, sw+idx); }
#pragma unroll
            for(int u=0;u<4;u++){ int idx=t+256*u; CPA(dst+16384+(u32)idx*16, st+idx); }
            CPC();
        }
        const uint4* XWfs=(const uint4*)(sm + p*32768);
        const uint4* XTfs=(const uint4*)(sm + p*32768 + 16384);
        float sacc[8][4]={};
#pragma unroll
        for(int qf=0;qf<4;qf++){
            u32 AL[4];
            AL[0]=PLs[(w*16+g  )*36 + qf*8+tc];
            AL[1]=PLs[(w*16+g+8)*36 + qf*8+tc];
            AL[2]=PLs[(w*16+g  )*36 + qf*8+tc+4];
            AL[3]=PLs[(w*16+g+8)*36 + qf*8+tc+4];
            const uint4* wb=XWfs + qf*256 + lane;
#pragma unroll
            for(int n=0;n<8;n++){
                uint4 v=wb[n*32];
                MMAH(sacc[n],PHr[qf],v.x,v.y);
                MMAH(sacc[n],PHr[qf],v.z,v.w);
                MMAH(sacc[n],AL,v.x,v.y);
            }
        }
#pragma unroll
        for(int qk=0;qk<4;qk++){
            u32 Sh[4],Sl[4];
#pragma unroll
            for(int qq=0;qq<2;qq++){
                const int n=2*qk+qq;
                const int kc=kt*64+n*8+2*tc;
                const float b0v=bas[kc], b1v=bas[kc+1];
                float s0=tanhf_(sacc[n][0]+rv0*b0v);
                float s1=tanhf_(sacc[n][1]+rv0*b1v);
                float s2=tanhf_(sacc[n][2]+rv1*b0v);
                float s3=tanhf_(sacc[n][3]+rv1*b1v);
                Sh[2*qq]  =cvt2h(s1,s0); Sl[2*qq]  =cvt2h(s1-fhi16(Sh[2*qq]),  s0-flo16(Sh[2*qq]));
                Sh[2*qq+1]=cvt2h(s3,s2); Sl[2*qq+1]=cvt2h(s3-fhi16(Sh[2*qq+1]),s2-flo16(Sh[2*qq+1]));
            }
            const uint4* tb=XTfs + qk*256 + lane;
#pragma unroll
            for(int n=0;n<8;n++){
                uint4 v=tb[n*32];
                MMAH(hacc[n],Sh,v.x,v.y);
                MMAH(hacc[n],Sh,v.z,v.w);
                MMAH(hacc[n],Sl,v.x,v.y);
            }
        }
    }

    // ---- epilogue ----
    {
        const int il=i0+w*16+g, ih=il+8;
#pragma unroll
        for(int n=0;n<8;n++){
            const int d=n*8+2*tc;
            float2 v0, v1;
            v0.x=hacc[n][0]+bW[d]; v0.y=hacc[n][1]+bW[d+1];
            v1.x=hacc[n][2]+bW[d]; v1.y=hacc[n][3]+bW[d+1];
            *(float2*)&H[((size_t)b*NN+il)*NF+d]=v0;
            *(float2*)&H[((size_t)b*NN+ih)*NF+d]=v1;
        }
    }
}

// ---------------------------------------------------------------------------
extern "C" void kernel_launch(void* const* d_in, const int* in_sizes, int n_in,
                              void* d_out, int out_size){
    const float* X =(const float*)d_in[0];
    const float* A =(const float*)d_in[1];
    const int*   N =(const int*)d_in[2];
    const float* W =(const float*)d_in[3];
    const float* a =(const float*)d_in[4];
    const float* bW=(const float*)d_in[5];
    const float* ba=(const float*)d_in[6];
    float* H=(float*)d_out;
    cudaFuncSetAttribute(k_main, cudaFuncAttributeMaxDynamicSharedMemorySize, SMEMB);
    k_prep<<<NB*8,256>>>(X,W,a);
    k_main<<<dim3(4,NB),256,SMEMB>>>(A,ba,bW,H,N);
}

// round 15
// speedup vs baseline: 1.8246x; 1.0292x over previous
#include <cuda_runtime.h>
typedef unsigned int u32; typedef unsigned long long u64; typedef unsigned short u16;
#define NB 64
#define NN 512
#define NF 64

__device__ float g_cs[NF];
__device__ __align__(16) u32  g_XWh [NB*NN*32];      // XW row-major f16x2 (diag adds)
__device__ __align__(16) uint4 g_XWfr[NB*8*4*8*32];  // [b][kt][qf][n][lane] f16 frags of XW (S-gemm B)
__device__ __align__(16) uint4 g_XTfr[NB*8*4*8*32];  // [b][kt][qk][n][lane] f16 frags of XW, k-dim=row
                                                     // (B operand of BOTH P-gemm and H-gemm)

__device__ __forceinline__ u32 smaddr(const void* p){
    u32 a; asm("{.reg .u64 t; cvta.to.shared.u64 t,%1; cvt.u32.u64 %0,t;}":"=r"(a):"l"(p)); return a;
}
__device__ __forceinline__ u32 cvt2h(float hi,float lo){ u32 r; asm("cvt.rn.f16x2.f32 %0,%1,%2;":"=r"(r):"f"(hi),"f"(lo)); return r; }
__device__ __forceinline__ float flo16(u32 p){ float f; asm("{.reg .b16 l,h; mov.b32 {l,h},%1; cvt.f32.f16 %0,l;}":"=f"(f):"r"(p)); return f; }
__device__ __forceinline__ float fhi16(u32 p){ float f; asm("{.reg .b16 l,h; mov.b32 {l,h},%1; cvt.f32.f16 %0,h;}":"=f"(f):"r"(p)); return f; }
__device__ __forceinline__ float tanhf_(float x){ float y; asm("tanh.approx.f32 %0,%1;":"=f"(y):"f"(x)); return y; }

#define MMAH(d,a,b0,b1) asm volatile( \
 "mma.sync.aligned.m16n8k16.row.col.f32.f16.f16.f32 {%0,%1,%2,%3},{%4,%5,%6,%7},{%8,%9},{%0,%1,%2,%3};" \
 : "+f"((d)[0]),"+f"((d)[1]),"+f"((d)[2]),"+f"((d)[3]) \
 : "r"((a)[0]),"r"((a)[1]),"r"((a)[2]),"r"((a)[3]),"r"(b0),"r"(b1))
#define CPA(dst,src) asm volatile("cp.async.cg.shared.global [%0],[%1],16;"::"r"(dst),"l"(src):"memory")
#define CPC() asm volatile("cp.async.commit_group;":::"memory")
#define CPW(n) asm volatile("cp.async.wait_group %0;"::"n"(n):"memory")

// ---------------------------------------------------------------------------
// XW = X@W per 64-row tile (f16 3-term MMA); col_sum(a) local -> g_cs; emit
// XW f16 row-major + 3-term fp16 k16 fragment packs (XWfr, XTfr).
__global__ __launch_bounds__(256) void k_prep(const float* __restrict__ X, const float* __restrict__ W,
                                              const float* __restrict__ am){
    __shared__ __align__(16) float Ws[64][64];
    __shared__ __align__(16) float Xs[64][68];
    __shared__ __align__(16) uint4 Wfr[4][8][32];
    __shared__ float csp[4][64];
    const int t=threadIdx.x, b=blockIdx.x>>3, kt=blockIdx.x&7, R0=blockIdx.x*64;
    const int w=t>>5, lane=t&31, g=lane>>2, tc=lane&3;
    {   // col_sum of a
        int f=t&63, seg=t>>6;
        float s=0.f;
        for(int i=seg;i<64;i+=4) s+=am[i*64+f];
        csp[seg][f]=s;
    }
    for(int i=t;i<64*64;i+=256) Ws[i>>6][i&63]=W[i];
    for(int i=t;i<64*64;i+=256) Xs[i>>6][i&63]=X[(size_t)(R0+(i>>6))*NF+(i&63)];
    __syncthreads();
    if(t<64) g_cs[t]=csp[0][t]+csp[1][t]+csp[2][t]+csp[3][t];
    // W B-fragments (f16 hi/lo, k16 chunks over input dim c)
    for(int u=t;u<1024;u+=256){
        int l2=u&31, n=(u>>5)&7, qc=u>>8;
        int gg=l2>>2, tcc=l2&3;
        int d=n*8+gg, c0=qc*16+2*tcc;
        float w0=Ws[c0][d], w1=Ws[c0+1][d], w2=Ws[c0+8][d], w3=Ws[c0+9][d];
        uint4 v;
        v.x=cvt2h(w1,w0); v.z=cvt2h(w1-fhi16(v.x), w0-flo16(v.x));
        v.y=cvt2h(w3,w2); v.w=cvt2h(w3-fhi16(v.y), w2-flo16(v.y));
        Wfr[qc][n][l2]=v;
    }
    __syncthreads();
    // XW = X@W via MMA: warp -> (m-frag w>>1, n-half w&1)
    const int mf=w>>1, nh=w&1;
    float acc[4][4]={};
#pragma unroll
    for(int qc=0;qc<4;qc++){
        float2 f0=*(float2*)&Xs[mf*16+g  ][qc*16+2*tc];
        float2 f1=*(float2*)&Xs[mf*16+g+8][qc*16+2*tc];
        float2 f2=*(float2*)&Xs[mf*16+g  ][qc*16+8+2*tc];
        float2 f3=*(float2*)&Xs[mf*16+g+8][qc*16+8+2*tc];
        u32 AH[4],AL[4];
        AH[0]=cvt2h(f0.y,f0.x); AL[0]=cvt2h(f0.y-fhi16(AH[0]), f0.x-flo16(AH[0]));
        AH[1]=cvt2h(f1.y,f1.x); AL[1]=cvt2h(f1.y-fhi16(AH[1]), f1.x-flo16(AH[1]));
        AH[2]=cvt2h(f2.y,f2.x); AL[2]=cvt2h(f2.y-fhi16(AH[2]), f2.x-flo16(AH[2]));
        AH[3]=cvt2h(f3.y,f3.x); AL[3]=cvt2h(f3.y-fhi16(AH[3]), f3.x-flo16(AH[3]));
#pragma unroll
        for(int nn=0;nn<4;nn++){
            uint4 v=Wfr[qc][nh*4+nn][lane];
            MMAH(acc[nn],AH,v.x,v.y);
            MMAH(acc[nn],AH,v.z,v.w);
            MMAH(acc[nn],AL,v.x,v.y);
        }
    }
    __syncthreads();   // all A-fragment reads of Xs done before overwrite
#pragma unroll
    for(int nn=0;nn<4;nn++){
        int d=(nh*4+nn)*8+2*tc;
        Xs[mf*16+g  ][d]=acc[nn][0]; Xs[mf*16+g  ][d+1]=acc[nn][1];
        Xs[mf*16+g+8][d]=acc[nn][2]; Xs[mf*16+g+8][d+1]=acc[nn][3];
    }
    __syncthreads();
    // XW f16 row-major (for diag adds in k_main)
#pragma unroll
    for(int u=0;u<8;u++){
        int idx=t+256*u; int r=idx>>5, c2=idx&31;
        g_XWh[(size_t)(R0+r)*32 + c2] = cvt2h(Xs[r][2*c2+1], Xs[r][2*c2]);
    }
    // XW frags (S-gemm B): col n*8+g = k row, chunk qf over f
#pragma unroll
    for(int u=0;u<4;u++){
        int idx=t+256*u; int n=(idx>>5)&7, qf=idx>>8;
        int k=n*8+g, f0=qf*16+2*tc;
        float x0=Xs[k][f0], x1=Xs[k][f0+1], x2=Xs[k][f0+8], x3=Xs[k][f0+9];
        uint4 v;
        v.x=cvt2h(x1,x0); v.z=cvt2h(x1-fhi16(v.x), x0-flo16(v.x));
        v.y=cvt2h(x3,x2); v.w=cvt2h(x3-fhi16(v.y), x2-flo16(v.y));
        g_XWfr[(((size_t)(b*8+kt)*4+qf)*8+n)*32+lane]=v;
    }
    // XT frags (P-gemm & H-gemm B): col n*8+g, chunk qk over rows
#pragma unroll
    for(int u=0;u<4;u++){
        int idx=t+256*u; int n=(idx>>5)&7, qk=idx>>8;
        int d=n*8+g, k0=qk*16+2*tc;
        float x0=Xs[k0][d], x1=Xs[k0+1][d], x2=Xs[k0+8][d], x3=Xs[k0+9][d];
        uint4 v;
        v.x=cvt2h(x1,x0); v.z=cvt2h(x1-fhi16(v.x), x0-flo16(v.x));
        v.y=cvt2h(x3,x2); v.w=cvt2h(x3-fhi16(v.y), x2-flo16(v.y));
        g_XTfr[(((size_t)(b*8+kt)*4+qk)*8+n)*32+lane]=v;
    }
}

// ---------------------------------------------------------------------------
// smem (bytes):
//  phase A: A0[0,18432) A1[18432,36864) Y0[36864,45056) Y1[45056,53248)
//  phase B overlay: buf0 XW@0 XT@16384 | buf1 XW@32768 XT@49152
//  PLs@65536 (18432) | rs@83968 (512) | bas@84480 (2048) | csm@86528 (256)
#define SMEMB 86784
__global__ __launch_bounds__(256,2) void k_main(const float* __restrict__ A, const float* __restrict__ ba,
                                                const float* __restrict__ bW, float* __restrict__ H,
                                                const int* __restrict__ N32){
    extern __shared__ __align__(16) char sm[];
    u32*  PLs=(u32*)(sm+65536);          // [128][36] f16x2 lo-residual pairs of P
    float* rs =(float*)(sm+83968);
    float* bas=(float*)(sm+84480);
    float* csm=(float*)(sm+86528);
    const int t=threadIdx.x, w=t>>5, lane=t&31, g=lane>>2, tc=lane&3;
    const int b=blockIdx.y, i0=blockIdx.x*128;
    const u32 sbase=smaddr(sm);
    bas[t]=ba[t]; bas[256+t]=ba[256+t];
    if(t<64) csm[t]=g_cs[t];
    const int nb = (__ldg(&N32[1])!=0) ? __ldg(&N32[b]) : __ldg(&N32[2*b]);
    const float* Ab = A + ((size_t)b*NN+i0)*NN;

    auto issueA=[&](int p,int it){
        const int j0=it*32;
#pragma unroll
        for(int u=0;u<4;u++){
            int idx=t+256*u; int r=idx>>3, c=idx&7;
            CPA(sbase + p*18432 + (u32)(r*36+c*4)*4, Ab + (size_t)r*NN + j0 + c*4);
        }
        const uint4* src=g_XTfr + (size_t)(b*32+it*2)*256;   // == Y-frag source (unscaled)
#pragma unroll
        for(int u=0;u<2;u++){
            int idx=t+256*u;
            CPA(sbase + 36864 + p*8192 + (u32)idx*16, src+idx);
        }
        CPC();
    };

    // ---- phase A: pacc = A @ XW over K=512 (cs applied in epilogue) ----
    float pacc[8][4]={}; float rloc=0.f;
    issueA(0,0);
    for(int it=0; it<16; it++){
        const int p=it&1;
        CPW(0);
        __syncthreads();           // publishes buf p; proves buf p^1 drained
        if(it<15) issueA(p^1,it+1);
        const float* As=(const float*)(sm + p*18432);
        if(t<128){
            float s=0.f;
#pragma unroll
            for(int c=0;c<8;c++){ float4 v=*(const float4*)&As[t*36+c*4]; s+=v.x+v.y+v.z+v.w; }
            rloc+=s;
        }
        const char* Yb = sm + 36864 + p*8192;
#pragma unroll
        for(int cc=0;cc<2;cc++){
            float2 f0=*(const float2*)&As[(w*16+g  )*36+cc*16+2*tc];
            float2 f1=*(const float2*)&As[(w*16+g+8)*36+cc*16+2*tc];
            float2 f2=*(const float2*)&As[(w*16+g  )*36+cc*16+8+2*tc];
            float2 f3=*(const float2*)&As[(w*16+g+8)*36+cc*16+8+2*tc];
            u32 AH[4],AL[4];
            AH[0]=cvt2h(f0.y,f0.x); AL[0]=cvt2h(f0.y-fhi16(AH[0]), f0.x-flo16(AH[0]));
            AH[1]=cvt2h(f1.y,f1.x); AL[1]=cvt2h(f1.y-fhi16(AH[1]), f1.x-flo16(AH[1]));
            AH[2]=cvt2h(f2.y,f2.x); AL[2]=cvt2h(f2.y-fhi16(AH[2]), f2.x-flo16(AH[2]));
            AH[3]=cvt2h(f3.y,f3.x); AL[3]=cvt2h(f3.y-fhi16(AH[3]), f3.x-flo16(AH[3]));
            const uint4* yb=(const uint4*)(Yb + cc*4096) + lane;
#pragma unroll
            for(int n=0;n<8;n++){
                uint4 v=yb[n*32];
                MMAH(pacc[n],AH,v.x,v.y);
                MMAH(pacc[n],AH,v.z,v.w);
                MMAH(pacc[n],AL,v.x,v.y);
            }
        }
    }
    if(t<128) rs[t]=rloc + ((i0+t)<nb ? 1.f : 0.f);
    __syncthreads();   // phase-A buffers fully drained before phase-B prefetch

    // ---- prefetch phase-B kt=0 into buf0 ----
    {
        const uint4* sw=g_XWfr + (size_t)(b*8)*1024;
        const uint4* st=g_XTfr + (size_t)(b*8)*1024;
#pragma unroll
        for(int u=0;u<4;u++){ int idx=t+256*u; CPA(sbase+(u32)idx*16, sw+idx); }
#pragma unroll
        for(int u=0;u<4;u++){ int idx=t+256*u; CPA(sbase+16384+(u32)idx*16, st+idx); }
        CPC();
    }

    // ---- diag add + cs scale; P hi-frags -> registers, lo -> smem ----
    u32 PHr[4][4];
    {
        const int il=i0+w*16+g, ih=il+8;
#pragma unroll
        for(int n=0;n<8;n++){
            const int f=n*8+2*tc;
            float d0=0.f,d1=0.f,e0=0.f,e1=0.f;
            if(il<nb){ u32 p=g_XWh[(size_t)(b*NN+il)*32 + n*4+tc]; d0=flo16(p); d1=fhi16(p); }
            if(ih<nb){ u32 p=g_XWh[(size_t)(b*NN+ih)*32 + n*4+tc]; e0=flo16(p); e1=fhi16(p); }
            const float c0=csm[f], c1=csm[f+1];
            pacc[n][0]=(pacc[n][0]+d0)*c0; pacc[n][1]=(pacc[n][1]+d1)*c1;
            pacc[n][2]=(pacc[n][2]+e0)*c0; pacc[n][3]=(pacc[n][3]+e1)*c1;
            u32 h0=cvt2h(pacc[n][1],pacc[n][0]);
            u32 l0=cvt2h(pacc[n][1]-fhi16(h0), pacc[n][0]-flo16(h0));
            u32 h1=cvt2h(pacc[n][3],pacc[n][2]);
            u32 l1=cvt2h(pacc[n][3]-fhi16(h1), pacc[n][2]-flo16(h1));
            PHr[n>>1][(n&1)?2:0]=h0;
            PHr[n>>1][(n&1)?3:1]=h1;
            PLs[(w*16+g  )*36 + n*4+tc]=l0;
            PLs[(w*16+g+8)*36 + n*4+tc]=l1;
        }
    }

    // ---- phase B: S = tanh(P@XW^T + r*ba); H += S@XW (3-term fp16, dbl-buffered) ----
    float hacc[8][4]={};
    float rv0=0.f, rv1=0.f;
    for(int kt=0;kt<8;kt++){
        const int p=kt&1;
        CPW(0);
        __syncthreads();           // publishes buf p (+ PLs/rs at kt=0); buf p^1 drained
        if(kt==0){ rv0=rs[w*16+g]; rv1=rs[w*16+g+8]; }
        if(kt<7){
            const uint4* sw=g_XWfr + (size_t)(b*8+kt+1)*1024;
            const uint4* st=g_XTfr + (size_t)(b*8+kt+1)*1024;
            const u32 dst=sbase+(u32)(p^1)*32768;
#pragma unroll
            for(int u=0;u<4;u++){ int idx=t+256*u; CPA(dst+(u32)idx*16, sw+idx); }
#pragma unroll
            for(int u=0;u<4;u++){ int idx=t+256*u; CPA(dst+16384+(u32)idx*16, st+idx); }
            CPC();
        }
        const uint4* XWfs=(const uint4*)(sm + p*32768);
        const uint4* XTfs=(const uint4*)(sm + p*32768 + 16384);
        float sacc[8][4]={};
#pragma unroll
        for(int qf=0;qf<4;qf++){
            u32 AL[4];
            AL[0]=PLs[(w*16+g  )*36 + qf*8+tc];
            AL[1]=PLs[(w*16+g+8)*36 + qf*8+tc];
            AL[2]=PLs[(w*16+g  )*36 + qf*8+tc+4];
            AL[3]=PLs[(w*16+g+8)*36 + qf*8+tc+4];
            const uint4* wb=XWfs + qf*256 + lane;
#pragma unroll
            for(int n=0;n<8;n++){
                uint4 v=wb[n*32];
                MMAH(sacc[n],PHr[qf],v.x,v.y);
                MMAH(sacc[n],PHr[qf],v.z,v.w);
                MMAH(sacc[n],AL,v.x,v.y);
            }
        }
#pragma unroll
        for(int qk=0;qk<4;qk++){
            u32 Sh[4],Sl[4];
#pragma unroll
            for(int qq=0;qq<2;qq++){
                const int n=2*qk+qq;
                const int kc=kt*64+n*8+2*tc;
                const float b0v=bas[kc], b1v=bas[kc+1];
                float s0=tanhf_(sacc[n][0]+rv0*b0v);
                float s1=tanhf_(sacc[n][1]+rv0*b1v);
                float s2=tanhf_(sacc[n][2]+rv1*b0v);
                float s3=tanhf_(sacc[n][3]+rv1*b1v);
                Sh[2*qq]  =cvt2h(s1,s0); Sl[2*qq]  =cvt2h(s1-fhi16(Sh[2*qq]),  s0-flo16(Sh[2*qq]));
                Sh[2*qq+1]=cvt2h(s3,s2); Sl[2*qq+1]=cvt2h(s3-fhi16(Sh[2*qq+1]),s2-flo16(Sh[2*qq+1]));
            }
            const uint4* tb=XTfs + qk*256 + lane;
#pragma unroll
            for(int n=0;n<8;n++){
                uint4 v=tb[n*32];
                MMAH(hacc[n],Sh,v.x,v.y);
                MMAH(hacc[n],Sh,v.z,v.w);
                MMAH(hacc[n],Sl,v.x,v.y);
            }
        }
    }

    // ---- epilogue ----
    {
        const int il=i0+w*16+g, ih=il+8;
#pragma unroll
        for(int n=0;n<8;n++){
            const int d=n*8+2*tc;
            float2 v0, v1;
            v0.x=hacc[n][0]+bW[d]; v0.y=hacc[n][1]+bW[d+1];
            v1.x=hacc[n][2]+bW[d]; v1.y=hacc[n][3]+bW[d+1];
            *(float2*)&H[((size_t)b*NN+il)*NF+d]=v0;
            *(float2*)&H[((size_t)b*NN+ih)*NF+d]=v1;
        }
    }
}

// ---------------------------------------------------------------------------
extern "C" void kernel_launch(void* const* d_in, const int* in_sizes, int n_in,
                              void* d_out, int out_size){
    const float* X =(const float*)d_in[0];
    const float* A =(const float*)d_in[1];
    const int*   N =(const int*)d_in[2];
    const float* W =(const float*)d_in[3];
    const float* a =(const float*)d_in[4];
    const float* bW=(const float*)d_in[5];
    const float* ba=(const float*)d_in[6];
    float* H=(float*)d_out;
    cudaFuncSetAttribute(k_main, cudaFuncAttributeMaxDynamicSharedMemorySize, SMEMB);
    k_prep<<<NB*8,256>>>(X,W,a);
    k_main<<<dim3(4,NB),256,SMEMB>>>(A,ba,bW,H,N);
}

// round 16
// speedup vs baseline: 1.9249x; 1.0550x over previous
#include <cuda_runtime.h>
typedef unsigned int u32; typedef unsigned long long u64; typedef unsigned short u16;
#define NB 64
#define NN 512
#define NF 64

__device__ float g_cs[NF];
__device__ __align__(16) u32  g_XWh [NB*NN*32];      // XW row-major f16x2 (diag adds)
__device__ __align__(16) uint4 g_XWfr[NB*8*4*8*32];  // [b][kt][qf][n][lane] f16 frags of XW (S-gemm B)
__device__ __align__(16) uint4 g_XTfr[NB*8*4*8*32];  // [b][kt][qk][n][lane] f16 frags of XW, k-dim=row
                                                     // (B operand of BOTH P-gemm and H-gemm)

__device__ __forceinline__ u32 smaddr(const void* p){
    u32 a; asm("{.reg .u64 t; cvta.to.shared.u64 t,%1; cvt.u32.u64 %0,t;}":"=r"(a):"l"(p)); return a;
}
__device__ __forceinline__ u32 cvt2h(float hi,float lo){ u32 r; asm("cvt.rn.f16x2.f32 %0,%1,%2;":"=r"(r):"f"(hi),"f"(lo)); return r; }
__device__ __forceinline__ float flo16(u32 p){ float f; asm("{.reg .b16 l,h; mov.b32 {l,h},%1; cvt.f32.f16 %0,l;}":"=f"(f):"r"(p)); return f; }
__device__ __forceinline__ float fhi16(u32 p){ float f; asm("{.reg .b16 l,h; mov.b32 {l,h},%1; cvt.f32.f16 %0,h;}":"=f"(f):"r"(p)); return f; }
__device__ __forceinline__ float tanhf_(float x){ float y; asm("tanh.approx.f32 %0,%1;":"=f"(y):"f"(x)); return y; }

#define MMAH(d,a,b0,b1) asm volatile( \
 "mma.sync.aligned.m16n8k16.row.col.f32.f16.f16.f32 {%0,%1,%2,%3},{%4,%5,%6,%7},{%8,%9},{%0,%1,%2,%3};" \
 : "+f"((d)[0]),"+f"((d)[1]),"+f"((d)[2]),"+f"((d)[3]) \
 : "r"((a)[0]),"r"((a)[1]),"r"((a)[2]),"r"((a)[3]),"r"(b0),"r"(b1))
#define CPA(dst,src) asm volatile("cp.async.cg.shared.global [%0],[%1],16;"::"r"(dst),"l"(src):"memory")
#define CPC() asm volatile("cp.async.commit_group;":::"memory")
#define CPW(n) asm volatile("cp.async.wait_group %0;"::"n"(n):"memory")

// ---------------------------------------------------------------------------
// XW = X@W per 64-row tile (f16 3-term MMA); col_sum(a) local -> g_cs; emit
// XW f16 row-major + 3-term fp16 k16 fragment packs (XWfr, XTfr).
__global__ __launch_bounds__(256) void k_prep(const float* __restrict__ X, const float* __restrict__ W,
                                              const float* __restrict__ am){
    __shared__ __align__(16) float Ws[64][64];
    __shared__ __align__(16) float Xs[64][68];
    __shared__ __align__(16) uint4 Wfr[4][8][32];
    __shared__ float csp[4][64];
    const int t=threadIdx.x, b=blockIdx.x>>3, kt=blockIdx.x&7, R0=blockIdx.x*64;
    const int w=t>>5, lane=t&31, g=lane>>2, tc=lane&3;
    {   // col_sum of a
        int f=t&63, seg=t>>6;
        float s=0.f;
        for(int i=seg;i<64;i+=4) s+=am[i*64+f];
        csp[seg][f]=s;
    }
    for(int i=t;i<64*64;i+=256) Ws[i>>6][i&63]=W[i];
    for(int i=t;i<64*64;i+=256) Xs[i>>6][i&63]=X[(size_t)(R0+(i>>6))*NF+(i&63)];
    __syncthreads();
    if(t<64) g_cs[t]=csp[0][t]+csp[1][t]+csp[2][t]+csp[3][t];
    // W B-fragments (f16 hi/lo, k16 chunks over input dim c)
    for(int u=t;u<1024;u+=256){
        int l2=u&31, n=(u>>5)&7, qc=u>>8;
        int gg=l2>>2, tcc=l2&3;
        int d=n*8+gg, c0=qc*16+2*tcc;
        float w0=Ws[c0][d], w1=Ws[c0+1][d], w2=Ws[c0+8][d], w3=Ws[c0+9][d];
        uint4 v;
        v.x=cvt2h(w1,w0); v.z=cvt2h(w1-fhi16(v.x), w0-flo16(v.x));
        v.y=cvt2h(w3,w2); v.w=cvt2h(w3-fhi16(v.y), w2-flo16(v.y));
        Wfr[qc][n][l2]=v;
    }
    __syncthreads();
    // XW = X@W via MMA: warp -> (m-frag w>>1, n-half w&1)
    const int mf=w>>1, nh=w&1;
    float acc[4][4]={};
#pragma unroll
    for(int qc=0;qc<4;qc++){
        float2 f0=*(float2*)&Xs[mf*16+g  ][qc*16+2*tc];
        float2 f1=*(float2*)&Xs[mf*16+g+8][qc*16+2*tc];
        float2 f2=*(float2*)&Xs[mf*16+g  ][qc*16+8+2*tc];
        float2 f3=*(float2*)&Xs[mf*16+g+8][qc*16+8+2*tc];
        u32 AH[4],AL[4];
        AH[0]=cvt2h(f0.y,f0.x); AL[0]=cvt2h(f0.y-fhi16(AH[0]), f0.x-flo16(AH[0]));
        AH[1]=cvt2h(f1.y,f1.x); AL[1]=cvt2h(f1.y-fhi16(AH[1]), f1.x-flo16(AH[1]));
        AH[2]=cvt2h(f2.y,f2.x); AL[2]=cvt2h(f2.y-fhi16(AH[2]), f2.x-flo16(AH[2]));
        AH[3]=cvt2h(f3.y,f3.x); AL[3]=cvt2h(f3.y-fhi16(AH[3]), f3.x-flo16(AH[3]));
#pragma unroll
        for(int nn=0;nn<4;nn++){
            uint4 v=Wfr[qc][nh*4+nn][lane];
            MMAH(acc[nn],AH,v.x,v.y);
            MMAH(acc[nn],AH,v.z,v.w);
            MMAH(acc[nn],AL,v.x,v.y);
        }
    }
    __syncthreads();   // all A-fragment reads of Xs done before overwrite
#pragma unroll
    for(int nn=0;nn<4;nn++){
        int d=(nh*4+nn)*8+2*tc;
        Xs[mf*16+g  ][d]=acc[nn][0]; Xs[mf*16+g  ][d+1]=acc[nn][1];
        Xs[mf*16+g+8][d]=acc[nn][2]; Xs[mf*16+g+8][d+1]=acc[nn][3];
    }
    __syncthreads();
    // XW f16 row-major (for diag adds in k_main)
#pragma unroll
    for(int u=0;u<8;u++){
        int idx=t+256*u; int r=idx>>5, c2=idx&31;
        g_XWh[(size_t)(R0+r)*32 + c2] = cvt2h(Xs[r][2*c2+1], Xs[r][2*c2]);
    }
    // XW frags (S-gemm B): col n*8+g = k row, chunk qf over f
#pragma unroll
    for(int u=0;u<4;u++){
        int idx=t+256*u; int n=(idx>>5)&7, qf=idx>>8;
        int k=n*8+g, f0=qf*16+2*tc;
        float x0=Xs[k][f0], x1=Xs[k][f0+1], x2=Xs[k][f0+8], x3=Xs[k][f0+9];
        uint4 v;
        v.x=cvt2h(x1,x0); v.z=cvt2h(x1-fhi16(v.x), x0-flo16(v.x));
        v.y=cvt2h(x3,x2); v.w=cvt2h(x3-fhi16(v.y), x2-flo16(v.y));
        g_XWfr[(((size_t)(b*8+kt)*4+qf)*8+n)*32+lane]=v;
    }
    // XT frags (P-gemm & H-gemm B): col n*8+g, chunk qk over rows
#pragma unroll
    for(int u=0;u<4;u++){
        int idx=t+256*u; int n=(idx>>5)&7, qk=idx>>8;
        int d=n*8+g, k0=qk*16+2*tc;
        float x0=Xs[k0][d], x1=Xs[k0+1][d], x2=Xs[k0+8][d], x3=Xs[k0+9][d];
        uint4 v;
        v.x=cvt2h(x1,x0); v.z=cvt2h(x1-fhi16(v.x), x0-flo16(v.x));
        v.y=cvt2h(x3,x2); v.w=cvt2h(x3-fhi16(v.y), x2-flo16(v.y));
        g_XTfr[(((size_t)(b*8+kt)*4+qk)*8+n)*32+lane]=v;
    }
}

// ---------------------------------------------------------------------------
// smem (bytes):
//  phase A: A0[0,18432) A1[18432,36864) Y0[36864,45056) Y1[45056,53248)
//  phase B overlay: buf0 XW@0 XT@16384 | buf1 XW@32768 XT@49152
//  PLs@65536 (18432) | rs@83968 (512) | bas@84480 (2048) | csm@86528 (256)
#define SMEMB 86784
__global__ __launch_bounds__(256,2) void k_main(const float* __restrict__ A, const float* __restrict__ ba,
                                                const float* __restrict__ bW, float* __restrict__ H,
                                                const int* __restrict__ N32){
    extern __shared__ __align__(16) char sm[];
    u32*  PLs=(u32*)(sm+65536);          // [128][36] f16x2 lo-residual pairs of P
    float* rs =(float*)(sm+83968);
    float* bas=(float*)(sm+84480);
    float* csm=(float*)(sm+86528);
    const int t=threadIdx.x, w=t>>5, lane=t&31, g=lane>>2, tc=lane&3;
    const int b=blockIdx.y, i0=blockIdx.x*128;
    const u32 sbase=smaddr(sm);
    bas[t]=ba[t]; bas[256+t]=ba[256+t];
    if(t<64) csm[t]=g_cs[t];
    const int nb = (__ldg(&N32[1])!=0) ? __ldg(&N32[b]) : __ldg(&N32[2*b]);
    const float* Ab = A + ((size_t)b*NN+i0)*NN;

    auto issueA=[&](int p,int it){
        const int j0=it*32;
#pragma unroll
        for(int u=0;u<4;u++){
            int idx=t+256*u; int r=idx>>3, c=idx&7;
            CPA(sbase + p*18432 + (u32)(r*36+c*4)*4, Ab + (size_t)r*NN + j0 + c*4);
        }
        const uint4* src=g_XTfr + (size_t)(b*32+it*2)*256;   // == Y-frag source (unscaled)
#pragma unroll
        for(int u=0;u<2;u++){
            int idx=t+256*u;
            CPA(sbase + 36864 + p*8192 + (u32)idx*16, src+idx);
        }
        CPC();
    };

    // ---- phase A: pacc = A @ XW over K=512 (cs applied in epilogue) ----
    float pacc[8][4]={}; float rloc=0.f;
    issueA(0,0);
    for(int it=0; it<16; it++){
        const int p=it&1;
        CPW(0);
        __syncthreads();           // publishes buf p; proves buf p^1 drained
        if(it<15) issueA(p^1,it+1);
        const float* As=(const float*)(sm + p*18432);
        if(t<128){
            float s=0.f;
#pragma unroll
            for(int c=0;c<8;c++){ float4 v=*(const float4*)&As[t*36+c*4]; s+=v.x+v.y+v.z+v.w; }
            rloc+=s;
        }
        const char* Yb = sm + 36864 + p*8192;
#pragma unroll
        for(int cc=0;cc<2;cc++){
            float2 f0=*(const float2*)&As[(w*16+g  )*36+cc*16+2*tc];
            float2 f1=*(const float2*)&As[(w*16+g+8)*36+cc*16+2*tc];
            float2 f2=*(const float2*)&As[(w*16+g  )*36+cc*16+8+2*tc];
            float2 f3=*(const float2*)&As[(w*16+g+8)*36+cc*16+8+2*tc];
            u32 AH[4],AL[4];
            AH[0]=cvt2h(f0.y,f0.x); AL[0]=cvt2h(f0.y-fhi16(AH[0]), f0.x-flo16(AH[0]));
            AH[1]=cvt2h(f1.y,f1.x); AL[1]=cvt2h(f1.y-fhi16(AH[1]), f1.x-flo16(AH[1]));
            AH[2]=cvt2h(f2.y,f2.x); AL[2]=cvt2h(f2.y-fhi16(AH[2]), f2.x-flo16(AH[2]));
            AH[3]=cvt2h(f3.y,f3.x); AL[3]=cvt2h(f3.y-fhi16(AH[3]), f3.x-flo16(AH[3]));
            const uint4* yb=(const uint4*)(Yb + cc*4096) + lane;
#pragma unroll
            for(int n=0;n<8;n++){
                uint4 v=yb[n*32];
                MMAH(pacc[n],AH,v.x,v.y);
                MMAH(pacc[n],AH,v.z,v.w);
                MMAH(pacc[n],AL,v.x,v.y);
            }
        }
    }
    if(t<128) rs[t]=rloc + ((i0+t)<nb ? 1.f : 0.f);
    __syncthreads();   // phase-A buffers fully drained before phase-B prefetch

    // ---- prefetch phase-B kt=0 into buf0 ----
    {
        const uint4* sw=g_XWfr + (size_t)(b*8)*1024;
        const uint4* st=g_XTfr + (size_t)(b*8)*1024;
#pragma unroll
        for(int u=0;u<4;u++){ int idx=t+256*u; CPA(sbase+(u32)idx*16, sw+idx); }
#pragma unroll
        for(int u=0;u<4;u++){ int idx=t+256*u; CPA(sbase+16384+(u32)idx*16, st+idx); }
        CPC();
    }

    // ---- diag add + cs scale; P hi-frags -> registers, lo -> smem ----
    u32 PHr[4][4];
    {
        const int il=i0+w*16+g, ih=il+8;
#pragma unroll
        for(int n=0;n<8;n++){
            const int f=n*8+2*tc;
            float d0=0.f,d1=0.f,e0=0.f,e1=0.f;
            if(il<nb){ u32 p=g_XWh[(size_t)(b*NN+il)*32 + n*4+tc]; d0=flo16(p); d1=fhi16(p); }
            if(ih<nb){ u32 p=g_XWh[(size_t)(b*NN+ih)*32 + n*4+tc]; e0=flo16(p); e1=fhi16(p); }
            const float c0=csm[f], c1=csm[f+1];
            pacc[n][0]=(pacc[n][0]+d0)*c0; pacc[n][1]=(pacc[n][1]+d1)*c1;
            pacc[n][2]=(pacc[n][2]+e0)*c0; pacc[n][3]=(pacc[n][3]+e1)*c1;
            u32 h0=cvt2h(pacc[n][1],pacc[n][0]);
            u32 l0=cvt2h(pacc[n][1]-fhi16(h0), pacc[n][0]-flo16(h0));
            u32 h1=cvt2h(pacc[n][3],pacc[n][2]);
            u32 l1=cvt2h(pacc[n][3]-fhi16(h1), pacc[n][2]-flo16(h1));
            PHr[n>>1][(n&1)?2:0]=h0;
            PHr[n>>1][(n&1)?3:1]=h1;
            PLs[(w*16+g  )*36 + n*4+tc]=l0;
            PLs[(w*16+g+8)*36 + n*4+tc]=l1;
        }
    }

    // ---- phase B: S = tanh(P@XW^T + r*ba); H += S@XW (Sh-only H-gemm, dbl-buffered) ----
    float hacc[8][4]={};
    float rv0=0.f, rv1=0.f;
    for(int kt=0;kt<8;kt++){
        const int p=kt&1;
        CPW(0);
        __syncthreads();           // publishes buf p (+ PLs/rs at kt=0); buf p^1 drained
        if(kt==0){ rv0=rs[w*16+g]; rv1=rs[w*16+g+8]; }
        if(kt<7){
            const uint4* sw=g_XWfr + (size_t)(b*8+kt+1)*1024;
            const uint4* st=g_XTfr + (size_t)(b*8+kt+1)*1024;
            const u32 dst=sbase+(u32)(p^1)*32768;
#pragma unroll
            for(int u=0;u<4;u++){ int idx=t+256*u; CPA(dst+(u32)idx*16, sw+idx); }
#pragma unroll
            for(int u=0;u<4;u++){ int idx=t+256*u; CPA(dst+16384+(u32)idx*16, st+idx); }
            CPC();
        }
        const uint4* XWfs=(const uint4*)(sm + p*32768);
        const uint4* XTfs=(const uint4*)(sm + p*32768 + 16384);
        float sacc[8][4]={};
#pragma unroll
        for(int qf=0;qf<4;qf++){
            u32 AL[4];
            AL[0]=PLs[(w*16+g  )*36 + qf*8+tc];
            AL[1]=PLs[(w*16+g+8)*36 + qf*8+tc];
            AL[2]=PLs[(w*16+g  )*36 + qf*8+tc+4];
            AL[3]=PLs[(w*16+g+8)*36 + qf*8+tc+4];
            const uint4* wb=XWfs + qf*256 + lane;
#pragma unroll
            for(int n=0;n<8;n++){
                uint4 v=wb[n*32];
                MMAH(sacc[n],PHr[qf],v.x,v.y);
                MMAH(sacc[n],PHr[qf],v.z,v.w);
                MMAH(sacc[n],AL,v.x,v.y);
            }
        }
#pragma unroll
        for(int qk=0;qk<4;qk++){
            u32 Sh[4];
#pragma unroll
            for(int qq=0;qq<2;qq++){
                const int n=2*qk+qq;
                const int kc=kt*64+n*8+2*tc;
                const float b0v=bas[kc], b1v=bas[kc+1];
                float s0=tanhf_(sacc[n][0]+rv0*b0v);
                float s1=tanhf_(sacc[n][1]+rv0*b1v);
                float s2=tanhf_(sacc[n][2]+rv1*b0v);
                float s3=tanhf_(sacc[n][3]+rv1*b1v);
                Sh[2*qq]  =cvt2h(s1,s0);
                Sh[2*qq+1]=cvt2h(s3,s2);
            }
            const uint4* tb=XTfs + qk*256 + lane;
#pragma unroll
            for(int n=0;n<8;n++){
                uint4 v=tb[n*32];
                MMAH(hacc[n],Sh,v.x,v.y);
                MMAH(hacc[n],Sh,v.z,v.w);
            }
        }
    }

    // ---- epilogue ----
    {
        const int il=i0+w*16+g, ih=il+8;
#pragma unroll
        for(int n=0;n<8;n++){
            const int d=n*8+2*tc;
            float2 v0, v1;
            v0.x=hacc[n][0]+bW[d]; v0.y=hacc[n][1]+bW[d+1];
            v1.x=hacc[n][2]+bW[d]; v1.y=hacc[n][3]+bW[d+1];
            *(float2*)&H[((size_t)b*NN+il)*NF+d]=v0;
            *(float2*)&H[((size_t)b*NN+ih)*NF+d]=v1;
        }
    }
}

// ---------------------------------------------------------------------------
extern "C" void kernel_launch(void* const* d_in, const int* in_sizes, int n_in,
                              void* d_out, int out_size){
    const float* X =(const float*)d_in[0];
    const float* A =(const float*)d_in[1];
    const int*   N =(const int*)d_in[2];
    const float* W =(const float*)d_in[3];
    const float* a =(const float*)d_in[4];
    const float* bW=(const float*)d_in[5];
    const float* ba=(const float*)d_in[6];
    float* H=(float*)d_out;
    cudaFuncSetAttribute(k_main, cudaFuncAttributeMaxDynamicSharedMemorySize, SMEMB);
    k_prep<<<NB*8,256>>>(X,W,a);
    k_main<<<dim3(4,NB),256,SMEMB>>>(A,ba,bW,H,N);
}